// round 6
// baseline (speedup 1.0000x reference)
#include <cuda_runtime.h>
#include <cuda_fp16.h>
#include <mma.h>
using namespace nvcuda;

#define DD 128
#define MAXN 100000
#define MAXE 1000000
#define NBLK_S 592
#define NBLK_O 444
#define TPB_E 256
#define WPB 8
#define BN_EPS 1e-5f

// ---------------- device scratch (no allocation allowed) ----------------
__device__ __half g_u[MAXN * DD];                // node proj, u-half (25.6 MB)
__device__ __half g_v[MAXN * DD];                // node proj, v-half (25.6 MB)
__device__ __align__(16) signed char g_u8[MAXN * DD];  // int8 u (12.8 MB)
__device__ __align__(16) signed char g_v8[MAXN * DD];  // int8 v (12.8 MB)
__device__ float g_su[MAXN];                     // per-node u scale
__device__ float g_sv[MAXN];                     // per-node v scale
__device__ __half g_xh[MAXN * DD];               // x in fp16 (25.6 MB)
__device__ __half g_w1h[128 * 256];              // W1 fused [k][out] fp16
__device__ int2  g_ei32[MAXE];                   // edge index as int32 (8 MB)
__device__ float g_part[256 * NBLK_S];           // transposed partials [feat][block]
__device__ float g_sums[256];                    // reduced [sum(128) | sumsq(128)]
__device__ float g_a[DD];                        // BN scale
__device__ float g_c[DD];                        // BN shift
__device__ int   g_idx64;                        // edge_index dtype flag

// ---------------- dtype detect: int64 edge_index has zero high words ----
__global__ void detect_idx_kernel(const int* __restrict__ ei) {
    int z = 0;
#pragma unroll
    for (int i = 0; i < 16; i++) z |= ei[2 * i + 1];
    g_idx64 = (z == 0) ? 1 : 0;
}

// ---------------- prep: edge index -> int32 ------------------------------
__global__ __launch_bounds__(256) void convert_idx_kernel(
    const long long* __restrict__ ei, int E) {
    int e = blockIdx.x * 256 + threadIdx.x;
    if (e >= E) return;
    int2 o;
    if (g_idx64) {
        longlong2 p = ((const longlong2*)ei)[e];
        o = make_int2((int)p.x, (int)p.y);
    } else {
        o = ((const int2*)ei)[e];
    }
    g_ei32[e] = o;
}

// ---------------- prep: x -> fp16 ---------------------------------------
__global__ __launch_bounds__(256) void x_to_half_kernel(
    const float* __restrict__ x, int total4) {
    int i = blockIdx.x * 256 + threadIdx.x;
    if (i < total4) {
        float4 f = ((const float4*)x)[i];
        __half2 a = __floats2half2_rn(f.x, f.y);
        __half2 b = __floats2half2_rn(f.z, f.w);
        uint2 o;
        o.x = *(unsigned int*)&a;
        o.y = *(unsigned int*)&b;
        ((uint2*)g_xh)[i] = o;
    }
}

// ---------------- prep: W1 -> fused fp16 [k 0..127][o 0..255] -----------
__global__ __launch_bounds__(256) void prep_w1_kernel(const float* __restrict__ W1) {
    int idx = blockIdx.x * 256 + threadIdx.x;
    if (idx < 128 * 256) {
        int k = idx >> 8, o = idx & 255;
        float val = (o < 128) ? W1[o * 256 + k] : W1[(o - 128) * 256 + 128 + k];
        g_w1h[k * 256 + o] = __float2half(val);
    }
}

// ---------------- node GEMM via tensor cores (wmma fp16, fp32 accum) ----
#define A_LD 72
#define B_LD 72
#define S_LD 36
__global__ __launch_bounds__(256) void node_gemm_mma_kernel(int N) {
    __shared__ char raw[8 * 32 * S_LD * 4];
    __half (*As)[A_LD] = (__half(*)[A_LD])raw;
    __half (*Bs)[B_LD] = (__half(*)[B_LD])(raw + 128 * A_LD * 2);

    const int tid = threadIdx.x;
    const int warp = tid >> 5;
    const int lane = tid & 31;
    const int base = blockIdx.x * 128;
    const int fblk = blockIdx.y;
    const int wr = warp >> 1;
    const int wc = warp & 1;

    wmma::fragment<wmma::accumulator, 16, 16, 16, float> acc[2][2];
#pragma unroll
    for (int r = 0; r < 2; r++)
#pragma unroll
        for (int c = 0; c < 2; c++) wmma::fill_fragment(acc[r][c], 0.f);

    for (int kc = 0; kc < 128; kc += 64) {
        __syncthreads();
#pragma unroll
        for (int it = 0; it < 8; it++) {
            int idx = it * 256 + tid;
            int r = idx >> 4;
            int c4 = idx & 15;
            int node = base + r;
            uint2 val = (node < N) ? ((const uint2*)&g_xh[node * 128 + kc])[c4]
                                   : make_uint2(0u, 0u);
            *(uint2*)&As[r][c4 * 4] = val;
        }
#pragma unroll
        for (int it = 0; it < 4; it++) {
            int idx = it * 256 + tid;
            int r = idx >> 4;
            int c4 = idx & 15;
            uint2 val = ((const uint2*)&g_w1h[(kc + r) * 256 + fblk * 64])[c4];
            *(uint2*)&Bs[r][c4 * 4] = val;
        }
        __syncthreads();
#pragma unroll
        for (int ks = 0; ks < 64; ks += 16) {
            wmma::fragment<wmma::matrix_a, 16, 16, 16, __half, wmma::row_major> af[2];
            wmma::fragment<wmma::matrix_b, 16, 16, 16, __half, wmma::row_major> bf[2];
            wmma::load_matrix_sync(af[0], &As[wr * 32][ks], A_LD);
            wmma::load_matrix_sync(af[1], &As[wr * 32 + 16][ks], A_LD);
            wmma::load_matrix_sync(bf[0], &Bs[ks][wc * 32], B_LD);
            wmma::load_matrix_sync(bf[1], &Bs[ks][wc * 32 + 16], B_LD);
#pragma unroll
            for (int r = 0; r < 2; r++)
#pragma unroll
                for (int c = 0; c < 2; c++)
                    wmma::mma_sync(acc[r][c], af[r], bf[c], acc[r][c]);
        }
    }

    __syncthreads();
    float (*stg)[S_LD] = (float(*)[S_LD])(raw + warp * 32 * S_LD * 4);
#pragma unroll
    for (int r = 0; r < 2; r++)
#pragma unroll
        for (int c = 0; c < 2; c++)
            wmma::store_matrix_sync(&stg[r * 16][c * 16], acc[r][c], S_LD,
                                    wmma::mem_row_major);
    __syncwarp();

    const int node = base + wr * 32 + lane;
    if (node < N) {
        const int o0 = fblk * 64 + wc * 32;
        __half* dst = (o0 < 128) ? &g_u[node * 128 + o0]
                                 : &g_v[node * 128 + (o0 - 128)];
        const float* srow = stg[lane];
#pragma unroll
        for (int c = 0; c < 32; c += 8) {
            __half2 h0 = __floats2half2_rn(srow[c + 0], srow[c + 1]);
            __half2 h1 = __floats2half2_rn(srow[c + 2], srow[c + 3]);
            __half2 h2 = __floats2half2_rn(srow[c + 4], srow[c + 5]);
            __half2 h3 = __floats2half2_rn(srow[c + 6], srow[c + 7]);
            uint4 o;
            o.x = *(unsigned int*)&h0;
            o.y = *(unsigned int*)&h1;
            o.z = *(unsigned int*)&h2;
            o.w = *(unsigned int*)&h3;
            *(uint4*)&dst[c] = o;
        }
    }
}

// ---------------- quantize u,v -> int8 with per-row scale ---------------
// One warp per row; rows [0,N)=u, [N,2N)=v. Lane: 4 halfs (uint2).
__global__ __launch_bounds__(256) void quant_uv_kernel(int N) {
    const int warp = threadIdx.x >> 5;
    const int lane = threadIdx.x & 31;
    const int row = blockIdx.x * 8 + warp;
    if (row >= 2 * N) return;
    const bool isv = row >= N;
    const int node = isv ? row - N : row;
    const __half* src = isv ? &g_v[node * 128] : &g_u[node * 128];

    uint2 p = ((const uint2*)src)[lane];
    __half2 h0 = *(__half2*)&p.x;
    __half2 h1 = *(__half2*)&p.y;
    float2 f0 = __half22float2(h0);
    float2 f1 = __half22float2(h1);
    float m = fmaxf(fmaxf(fabsf(f0.x), fabsf(f0.y)),
                    fmaxf(fabsf(f1.x), fabsf(f1.y)));
#pragma unroll
    for (int o = 16; o > 0; o >>= 1)
        m = fmaxf(m, __shfl_xor_sync(0xFFFFFFFFu, m, o));
    m = fmaxf(m, 1e-20f);
    const float inv = 127.f / m;

    int b0 = (int)rintf(f0.x * inv) & 255;
    int b1 = (int)rintf(f0.y * inv) & 255;
    int b2 = (int)rintf(f1.x * inv) & 255;
    int b3 = (int)rintf(f1.y * inv) & 255;
    unsigned packed = (unsigned)(b0 | (b1 << 8) | (b2 << 16) | (b3 << 24));

    signed char* dst8 = isv ? &g_v8[node * 128] : &g_u8[node * 128];
    ((unsigned*)dst8)[lane] = packed;
    if (lane == 0) {
        if (isv) g_sv[node] = m * (1.f / 127.f);
        else     g_su[node] = m * (1.f / 127.f);
    }
}

// ---------------- dp4a byte extract (signed) -----------------------------
__device__ __forceinline__ float s8tof(unsigned p, int i) {
    int r;
    asm("dp4a.s32.s32 %0, %1, %2, %3;" : "=r"(r)
        : "r"(p), "r"(1 << (8 * i)), "r"(0));
    return (float)r;
}

// ---------------- edge pass 1: stats from int8. 16 lanes/edge -----------
__global__ __launch_bounds__(TPB_E) void edge_stats_kernel(int E, int stride) {
    const int lane = threadIdx.x & 31;
    const int hl = lane & 15;
    const int half = lane >> 4;
    const int wid = threadIdx.x >> 5;
    const int gw = blockIdx.x * WPB + wid;

    float s[8], q[8];
#pragma unroll
    for (int j = 0; j < 8; j++) { s[j] = 0.f; q[j] = 0.f; }

    const uint2* __restrict__ U = (const uint2*)g_u8;    // 16 uint2 per row
    const uint2* __restrict__ V = (const uint2*)g_v8;
    const int4* __restrict__ EI = (const int4*)g_ei32;

#pragma unroll 2
    for (int it = gw * 2; it < E; it += stride) {
        int4 idx = EI[it >> 1];
        int src = half ? idx.z : idx.x;
        int dst = half ? idx.w : idx.y;
        float su = g_su[src];
        float sv = g_sv[dst];
        uint2 up = U[src * 16 + hl];                     // 8 int8 feats
        uint2 vp = V[dst * 16 + hl];
#pragma unroll
        for (int h = 0; h < 2; h++) {
            unsigned uw = h ? up.y : up.x;
            unsigned vw = h ? vp.y : vp.x;
#pragma unroll
            for (int b = 0; b < 4; b++) {
                int j = h * 4 + b;
                float w = su * s8tof(uw, b) + sv * s8tof(vw, b);
                s[j] += w;
                q[j] = fmaf(w, w, q[j]);
            }
        }
    }

    __shared__ float red[WPB * 256];
    float* r = red + wid * 256;
    if (half == 0) {
#pragma unroll
        for (int j = 0; j < 8; j++) { r[hl * 8 + j] = s[j]; r[128 + hl * 8 + j] = q[j]; }
    }
    __syncwarp();
    if (half == 1) {
#pragma unroll
        for (int j = 0; j < 8; j++) { r[hl * 8 + j] += s[j]; r[128 + hl * 8 + j] += q[j]; }
    }
    __syncthreads();
    int j = threadIdx.x;
    float t = 0.f;
#pragma unroll
    for (int w = 0; w < WPB; w++) t += red[w * 256 + j];
    g_part[j * NBLK_S + blockIdx.x] = t;
}

// ---------------- parallel partial reduction: 256 blocks ----------------
__global__ __launch_bounds__(256) void reduce_partials_kernel() {
    const int j = blockIdx.x;
    const int t = threadIdx.x;
    float s = 0.f;
    for (int b = t; b < NBLK_S; b += 256) s += g_part[j * NBLK_S + b];
    __shared__ float red[256];
    red[t] = s;
    __syncthreads();
#pragma unroll
    for (int o = 128; o >= 32; o >>= 1) {
        if (t < o) red[t] += red[t + o];
        __syncthreads();
    }
    if (t < 32) {
        float v = red[t];
#pragma unroll
        for (int o = 16; o > 0; o >>= 1) v += __shfl_xor_sync(0xFFFFFFFFu, v, o);
        if (t == 0) g_sums[j] = v;
    }
}

// ---------------- finalize BN affine ------------------------------------
__global__ void finalize_stats_kernel(const float* __restrict__ gamma,
                                      const float* __restrict__ beta,
                                      float invE) {
    int j = threadIdx.x;
    float mean = g_sums[j] * invE;
    float var = fmaf(-mean, mean, g_sums[128 + j] * invE);
    float a = gamma[j] * rsqrtf(var + BN_EPS);
    g_a[j] = a;
    g_c[j] = fmaf(-a, mean, beta[j]);
}

// ---------------- edge pass 2: out (fp16 u,v). 16 lanes/edge ------------
__global__ __launch_bounds__(TPB_E) void edge_out_kernel(
    const float* __restrict__ W2, const float* __restrict__ b2,
    float* __restrict__ out, int E, int stride) {
    const int lane = threadIdx.x & 31;
    const int hl = lane & 15;
    const int half = lane >> 4;
    const int gw = blockIdx.x * WPB + (threadIdx.x >> 5);

    float a[8], c[8], wa[8], wb[8];
    {
        float4 t0 = *(const float4*)&g_a[hl * 8];
        float4 t1 = *(const float4*)&g_a[hl * 8 + 4];
        a[0]=t0.x; a[1]=t0.y; a[2]=t0.z; a[3]=t0.w;
        a[4]=t1.x; a[5]=t1.y; a[6]=t1.z; a[7]=t1.w;
        t0 = *(const float4*)&g_c[hl * 8];
        t1 = *(const float4*)&g_c[hl * 8 + 4];
        c[0]=t0.x; c[1]=t0.y; c[2]=t0.z; c[3]=t0.w;
        c[4]=t1.x; c[5]=t1.y; c[6]=t1.z; c[7]=t1.w;
        t0 = *(const float4*)&W2[hl * 8];
        t1 = *(const float4*)&W2[hl * 8 + 4];
        wa[0]=t0.x; wa[1]=t0.y; wa[2]=t0.z; wa[3]=t0.w;
        wa[4]=t1.x; wa[5]=t1.y; wa[6]=t1.z; wa[7]=t1.w;
        t0 = *(const float4*)&W2[128 + hl * 8];
        t1 = *(const float4*)&W2[128 + hl * 8 + 4];
        wb[0]=t0.x; wb[1]=t0.y; wb[2]=t0.z; wb[3]=t0.w;
        wb[4]=t1.x; wb[5]=t1.y; wb[6]=t1.z; wb[7]=t1.w;
    }
    const float bz0 = b2[0], bz1 = b2[1];

    const uint4* __restrict__ U = (const uint4*)g_u;
    const uint4* __restrict__ V = (const uint4*)g_v;
    const int4* __restrict__ EI = (const int4*)g_ei32;

#pragma unroll 4
    for (int it = gw * 2; it < E; it += stride) {
        int4 idx = EI[it >> 1];
        int src = half ? idx.z : idx.x;
        int dst = half ? idx.w : idx.y;
        uint4 ur = U[src * 16 + hl];
        uint4 vr = V[dst * 16 + hl];
        float2 u0 = __half22float2(*(__half2*)&ur.x);
        float2 u1 = __half22float2(*(__half2*)&ur.y);
        float2 u2 = __half22float2(*(__half2*)&ur.z);
        float2 u3 = __half22float2(*(__half2*)&ur.w);
        float2 v0 = __half22float2(*(__half2*)&vr.x);
        float2 v1 = __half22float2(*(__half2*)&vr.y);
        float2 v2 = __half22float2(*(__half2*)&vr.z);
        float2 v3 = __half22float2(*(__half2*)&vr.w);
        float w[8];
        w[0] = u0.x + v0.x; w[1] = u0.y + v0.y;
        w[2] = u1.x + v1.x; w[3] = u1.y + v1.y;
        w[4] = u2.x + v2.x; w[5] = u2.y + v2.y;
        w[6] = u3.x + v3.x; w[7] = u3.y + v3.y;
        float p0 = 0.f, p1 = 0.f;
#pragma unroll
        for (int j = 0; j < 8; j++) {
            float rr = fmaxf(fmaf(a[j], w[j], c[j]), 0.f);
            p0 = fmaf(rr, wa[j], p0);
            p1 = fmaf(rr, wb[j], p1);
        }
#pragma unroll
        for (int o = 8; o > 0; o >>= 1) {
            p0 += __shfl_xor_sync(0xFFFFFFFFu, p0, o);
            p1 += __shfl_xor_sync(0xFFFFFFFFu, p1, o);
        }
        if (hl == 0)
            ((float2*)out)[it + half] = make_float2(p0 + bz0, p1 + bz1);
    }
}

// ---------------- launch ------------------------------------------------
extern "C" void kernel_launch(void* const* d_in, const int* in_sizes, int n_in,
                              void* d_out, int out_size) {
    const float* x = (const float*)d_in[0];
    const long long* ei = (const long long*)d_in[1];
    const float* W1 = (const float*)d_in[2];
    // d_in[3] = b1 : cancels inside BatchNorm, unused
    const float* gamma = (const float*)d_in[4];
    const float* beta = (const float*)d_in[5];
    const float* W2 = (const float*)d_in[6];
    const float* b2 = (const float*)d_in[7];

    const int N = in_sizes[0] / DD;
    const int E = in_sizes[1] / 2;
    const int total4 = N * DD / 4;

    detect_idx_kernel<<<1, 1>>>((const int*)ei);
    convert_idx_kernel<<<(E + 255) / 256, 256>>>(ei, E);
    x_to_half_kernel<<<(total4 + 255) / 256, 256>>>(x, total4);
    prep_w1_kernel<<<128, 256>>>(W1);
    dim3 ggrid((N + 127) / 128, 4);
    node_gemm_mma_kernel<<<ggrid, 256>>>(N);
    quant_uv_kernel<<<(2 * N + 7) / 8, 256>>>(N);
    edge_stats_kernel<<<NBLK_S, TPB_E>>>(E, NBLK_S * WPB * 2);
    reduce_partials_kernel<<<256, 256>>>();
    finalize_stats_kernel<<<1, 128>>>(gamma, beta, 1.0f / (float)E);
    edge_out_kernel<<<NBLK_O, TPB_E>>>(W2, b2, (float*)d_out, E, NBLK_O * WPB * 2);
}

// round 7
// speedup vs baseline: 1.3643x; 1.3643x over previous
#include <cuda_runtime.h>
#include <cuda_fp16.h>
#include <mma.h>
using namespace nvcuda;

#define DD 128
#define MAXN 100000
#define MAXE 1000000
#define NBLK_E 1184
#define TPB_E 256
#define WPB 8
#define BN_EPS 1e-5f

// ---------------- device scratch (no allocation allowed) ----------------
__device__ __half g_u[MAXN * DD];                // node proj, u-half (25.6 MB)
__device__ __half g_v[MAXN * DD];                // node proj, v-half (25.6 MB)
__device__ __half g_xh[MAXN * DD];               // x in fp16 (25.6 MB)
__device__ __half g_w1h[128 * 256];              // W1 fused [k][out] fp16
__device__ int2  g_ei32[MAXE];                   // edge index as int32 (8 MB)
__device__ float g_part[256 * NBLK_E];           // transposed partials [feat][block]
__device__ float g_a[DD];                        // BN scale
__device__ float g_c[DD];                        // BN shift

// ---------------- prep: edge index -> int32 (self-detecting dtype) ------
__global__ __launch_bounds__(256) void convert_idx_kernel(
    const long long* __restrict__ ei, int E) {
    // int64 edge_index (values < 2^31) has zero high dwords in first 16 slots
    const int* eiv = (const int*)ei;
    int z = 0;
#pragma unroll
    for (int i = 0; i < 16; i++) z |= eiv[2 * i + 1];
    const bool is64 = (z == 0);

    int e = blockIdx.x * 256 + threadIdx.x;
    if (e >= E) return;
    int2 o;
    if (is64) {
        longlong2 p = ((const longlong2*)ei)[e];
        o = make_int2((int)p.x, (int)p.y);
    } else {
        o = ((const int2*)ei)[e];
    }
    g_ei32[e] = o;
}

// ---------------- prep: x -> fp16 ---------------------------------------
__global__ __launch_bounds__(256) void x_to_half_kernel(
    const float* __restrict__ x, int total4) {
    int i = blockIdx.x * 256 + threadIdx.x;
    if (i < total4) {
        float4 f = ((const float4*)x)[i];
        __half2 a = __floats2half2_rn(f.x, f.y);
        __half2 b = __floats2half2_rn(f.z, f.w);
        uint2 o;
        o.x = *(unsigned int*)&a;
        o.y = *(unsigned int*)&b;
        ((uint2*)g_xh)[i] = o;
    }
}

// ---------------- prep: W1 -> fused fp16 [k 0..127][o 0..255] -----------
__global__ __launch_bounds__(256) void prep_w1_kernel(const float* __restrict__ W1) {
    int idx = blockIdx.x * 256 + threadIdx.x;
    if (idx < 128 * 256) {
        int k = idx >> 8, o = idx & 255;
        float val = (o < 128) ? W1[o * 256 + k] : W1[(o - 128) * 256 + 128 + k];
        g_w1h[k * 256 + o] = __float2half(val);
    }
}

// ---------------- node GEMM via tensor cores (wmma fp16, fp32 accum) ----
#define A_LD 72
#define B_LD 72
#define S_LD 36
__global__ __launch_bounds__(256) void node_gemm_mma_kernel(int N) {
    __shared__ char raw[8 * 32 * S_LD * 4];
    __half (*As)[A_LD] = (__half(*)[A_LD])raw;
    __half (*Bs)[B_LD] = (__half(*)[B_LD])(raw + 128 * A_LD * 2);

    const int tid = threadIdx.x;
    const int warp = tid >> 5;
    const int lane = tid & 31;
    const int base = blockIdx.x * 128;
    const int fblk = blockIdx.y;
    const int wr = warp >> 1;
    const int wc = warp & 1;

    wmma::fragment<wmma::accumulator, 16, 16, 16, float> acc[2][2];
#pragma unroll
    for (int r = 0; r < 2; r++)
#pragma unroll
        for (int c = 0; c < 2; c++) wmma::fill_fragment(acc[r][c], 0.f);

    for (int kc = 0; kc < 128; kc += 64) {
        __syncthreads();
#pragma unroll
        for (int it = 0; it < 8; it++) {
            int idx = it * 256 + tid;
            int r = idx >> 4;
            int c4 = idx & 15;
            int node = base + r;
            uint2 val = (node < N) ? ((const uint2*)&g_xh[node * 128 + kc])[c4]
                                   : make_uint2(0u, 0u);
            *(uint2*)&As[r][c4 * 4] = val;
        }
#pragma unroll
        for (int it = 0; it < 4; it++) {
            int idx = it * 256 + tid;
            int r = idx >> 4;
            int c4 = idx & 15;
            uint2 val = ((const uint2*)&g_w1h[(kc + r) * 256 + fblk * 64])[c4];
            *(uint2*)&Bs[r][c4 * 4] = val;
        }
        __syncthreads();
#pragma unroll
        for (int ks = 0; ks < 64; ks += 16) {
            wmma::fragment<wmma::matrix_a, 16, 16, 16, __half, wmma::row_major> af[2];
            wmma::fragment<wmma::matrix_b, 16, 16, 16, __half, wmma::row_major> bf[2];
            wmma::load_matrix_sync(af[0], &As[wr * 32][ks], A_LD);
            wmma::load_matrix_sync(af[1], &As[wr * 32 + 16][ks], A_LD);
            wmma::load_matrix_sync(bf[0], &Bs[ks][wc * 32], B_LD);
            wmma::load_matrix_sync(bf[1], &Bs[ks][wc * 32 + 16], B_LD);
#pragma unroll
            for (int r = 0; r < 2; r++)
#pragma unroll
                for (int c = 0; c < 2; c++)
                    wmma::mma_sync(acc[r][c], af[r], bf[c], acc[r][c]);
        }
    }

    __syncthreads();
    float (*stg)[S_LD] = (float(*)[S_LD])(raw + warp * 32 * S_LD * 4);
#pragma unroll
    for (int r = 0; r < 2; r++)
#pragma unroll
        for (int c = 0; c < 2; c++)
            wmma::store_matrix_sync(&stg[r * 16][c * 16], acc[r][c], S_LD,
                                    wmma::mem_row_major);
    __syncwarp();

    const int node = base + wr * 32 + lane;
    if (node < N) {
        const int o0 = fblk * 64 + wc * 32;
        __half* dst = (o0 < 128) ? &g_u[node * 128 + o0]
                                 : &g_v[node * 128 + (o0 - 128)];
        const float* srow = stg[lane];
#pragma unroll
        for (int c = 0; c < 32; c += 8) {
            __half2 h0 = __floats2half2_rn(srow[c + 0], srow[c + 1]);
            __half2 h1 = __floats2half2_rn(srow[c + 2], srow[c + 3]);
            __half2 h2 = __floats2half2_rn(srow[c + 4], srow[c + 5]);
            __half2 h3 = __floats2half2_rn(srow[c + 6], srow[c + 7]);
            uint4 o;
            o.x = *(unsigned int*)&h0;
            o.y = *(unsigned int*)&h1;
            o.z = *(unsigned int*)&h2;
            o.w = *(unsigned int*)&h3;
            *(uint4*)&dst[c] = o;
        }
    }
}

// ---------------- edge pass 1: stats. 16 lanes/edge, 2 edges/warp -------
__global__ __launch_bounds__(TPB_E) void edge_stats_kernel(int E, int stride) {
    const int lane = threadIdx.x & 31;
    const int hl = lane & 15;
    const int half = lane >> 4;
    const int wid = threadIdx.x >> 5;
    const int gw = blockIdx.x * WPB + wid;

    float s[8], q[8];
#pragma unroll
    for (int j = 0; j < 8; j++) { s[j] = 0.f; q[j] = 0.f; }

    const uint4* __restrict__ U = (const uint4*)g_u;
    const uint4* __restrict__ V = (const uint4*)g_v;
    const int4* __restrict__ EI = (const int4*)g_ei32;

#pragma unroll 4
    for (int it = gw * 2; it < E; it += stride) {
        int4 idx = EI[it >> 1];                 // broadcast: edges it, it+1
        int src = half ? idx.z : idx.x;
        int dst = half ? idx.w : idx.y;
        uint4 ur = U[src * 16 + hl];
        uint4 vr = V[dst * 16 + hl];
        float2 u0 = __half22float2(*(__half2*)&ur.x);
        float2 u1 = __half22float2(*(__half2*)&ur.y);
        float2 u2 = __half22float2(*(__half2*)&ur.z);
        float2 u3 = __half22float2(*(__half2*)&ur.w);
        float2 v0 = __half22float2(*(__half2*)&vr.x);
        float2 v1 = __half22float2(*(__half2*)&vr.y);
        float2 v2 = __half22float2(*(__half2*)&vr.z);
        float2 v3 = __half22float2(*(__half2*)&vr.w);
        float w[8];
        w[0] = u0.x + v0.x; w[1] = u0.y + v0.y;
        w[2] = u1.x + v1.x; w[3] = u1.y + v1.y;
        w[4] = u2.x + v2.x; w[5] = u2.y + v2.y;
        w[6] = u3.x + v3.x; w[7] = u3.y + v3.y;
#pragma unroll
        for (int j = 0; j < 8; j++) {
            s[j] += w[j];
            q[j] = fmaf(w[j], w[j], q[j]);
        }
    }

    __shared__ float red[WPB * 256];
    float* r = red + wid * 256;
    if (half == 0) {
#pragma unroll
        for (int j = 0; j < 8; j++) { r[hl * 8 + j] = s[j]; r[128 + hl * 8 + j] = q[j]; }
    }
    __syncwarp();
    if (half == 1) {
#pragma unroll
        for (int j = 0; j < 8; j++) { r[hl * 8 + j] += s[j]; r[128 + hl * 8 + j] += q[j]; }
    }
    __syncthreads();
    int j = threadIdx.x;
    float t = 0.f;
#pragma unroll
    for (int w = 0; w < WPB; w++) t += red[w * 256 + j];
    g_part[j * NBLK_E + blockIdx.x] = t;
}

// ---------------- fused reduce + BN finalize: 128 blocks ----------------
__global__ __launch_bounds__(256) void reduce_finalize_kernel(
    const float* __restrict__ gamma, const float* __restrict__ beta,
    float invE) {
    const int j = blockIdx.x;              // feature 0..127
    const int t = threadIdx.x;
    float s = 0.f, q = 0.f;
    for (int b = t; b < NBLK_E; b += 256) {
        s += g_part[j * NBLK_E + b];
        q += g_part[(128 + j) * NBLK_E + b];
    }
    __shared__ float rs[256], rq[256];
    rs[t] = s; rq[t] = q;
    __syncthreads();
#pragma unroll
    for (int o = 128; o >= 32; o >>= 1) {
        if (t < o) { rs[t] += rs[t + o]; rq[t] += rq[t + o]; }
        __syncthreads();
    }
    if (t < 32) {
        float vs = rs[t], vq = rq[t];
#pragma unroll
        for (int o = 16; o > 0; o >>= 1) {
            vs += __shfl_xor_sync(0xFFFFFFFFu, vs, o);
            vq += __shfl_xor_sync(0xFFFFFFFFu, vq, o);
        }
        if (t == 0) {
            float mean = vs * invE;
            float var = fmaf(-mean, mean, vq * invE);
            float a = gamma[j] * rsqrtf(var + BN_EPS);
            g_a[j] = a;
            g_c[j] = fmaf(-a, mean, beta[j]);
        }
    }
}

// ---------------- edge pass 2: out. 16 lanes/edge, 2 edges/warp ---------
__global__ __launch_bounds__(TPB_E) void edge_out_kernel(
    const float* __restrict__ W2, const float* __restrict__ b2,
    float* __restrict__ out, int E, int stride) {
    const int lane = threadIdx.x & 31;
    const int hl = lane & 15;
    const int half = lane >> 4;
    const int gw = blockIdx.x * WPB + (threadIdx.x >> 5);

    float a[8], c[8], wa[8], wb[8];
    {
        float4 t0 = *(const float4*)&g_a[hl * 8];
        float4 t1 = *(const float4*)&g_a[hl * 8 + 4];
        a[0]=t0.x; a[1]=t0.y; a[2]=t0.z; a[3]=t0.w;
        a[4]=t1.x; a[5]=t1.y; a[6]=t1.z; a[7]=t1.w;
        t0 = *(const float4*)&g_c[hl * 8];
        t1 = *(const float4*)&g_c[hl * 8 + 4];
        c[0]=t0.x; c[1]=t0.y; c[2]=t0.z; c[3]=t0.w;
        c[4]=t1.x; c[5]=t1.y; c[6]=t1.z; c[7]=t1.w;
        t0 = *(const float4*)&W2[hl * 8];
        t1 = *(const float4*)&W2[hl * 8 + 4];
        wa[0]=t0.x; wa[1]=t0.y; wa[2]=t0.z; wa[3]=t0.w;
        wa[4]=t1.x; wa[5]=t1.y; wa[6]=t1.z; wa[7]=t1.w;
        t0 = *(const float4*)&W2[128 + hl * 8];
        t1 = *(const float4*)&W2[128 + hl * 8 + 4];
        wb[0]=t0.x; wb[1]=t0.y; wb[2]=t0.z; wb[3]=t0.w;
        wb[4]=t1.x; wb[5]=t1.y; wb[6]=t1.z; wb[7]=t1.w;
    }
    const float bz0 = b2[0], bz1 = b2[1];

    const uint4* __restrict__ U = (const uint4*)g_u;
    const uint4* __restrict__ V = (const uint4*)g_v;
    const int4* __restrict__ EI = (const int4*)g_ei32;

#pragma unroll 4
    for (int it = gw * 2; it < E; it += stride) {
        int4 idx = EI[it >> 1];
        int src = half ? idx.z : idx.x;
        int dst = half ? idx.w : idx.y;
        uint4 ur = U[src * 16 + hl];
        uint4 vr = V[dst * 16 + hl];
        float2 u0 = __half22float2(*(__half2*)&ur.x);
        float2 u1 = __half22float2(*(__half2*)&ur.y);
        float2 u2 = __half22float2(*(__half2*)&ur.z);
        float2 u3 = __half22float2(*(__half2*)&ur.w);
        float2 v0 = __half22float2(*(__half2*)&vr.x);
        float2 v1 = __half22float2(*(__half2*)&vr.y);
        float2 v2 = __half22float2(*(__half2*)&vr.z);
        float2 v3 = __half22float2(*(__half2*)&vr.w);
        float w[8];
        w[0] = u0.x + v0.x; w[1] = u0.y + v0.y;
        w[2] = u1.x + v1.x; w[3] = u1.y + v1.y;
        w[4] = u2.x + v2.x; w[5] = u2.y + v2.y;
        w[6] = u3.x + v3.x; w[7] = u3.y + v3.y;
        float p0 = 0.f, p1 = 0.f;
#pragma unroll
        for (int j = 0; j < 8; j++) {
            float rr = fmaxf(fmaf(a[j], w[j], c[j]), 0.f);
            p0 = fmaf(rr, wa[j], p0);
            p1 = fmaf(rr, wb[j], p1);
        }
#pragma unroll
        for (int o = 8; o > 0; o >>= 1) {
            p0 += __shfl_xor_sync(0xFFFFFFFFu, p0, o);
            p1 += __shfl_xor_sync(0xFFFFFFFFu, p1, o);
        }
        if (hl == 0)
            ((float2*)out)[it + half] = make_float2(p0 + bz0, p1 + bz1);
    }
}

// ---------------- launch ------------------------------------------------
extern "C" void kernel_launch(void* const* d_in, const int* in_sizes, int n_in,
                              void* d_out, int out_size) {
    const float* x = (const float*)d_in[0];
    const long long* ei = (const long long*)d_in[1];
    const float* W1 = (const float*)d_in[2];
    // d_in[3] = b1 : cancels inside BatchNorm, unused
    const float* gamma = (const float*)d_in[4];
    const float* beta = (const float*)d_in[5];
    const float* W2 = (const float*)d_in[6];
    const float* b2 = (const float*)d_in[7];

    const int N = in_sizes[0] / DD;
    const int E = in_sizes[1] / 2;
    const int total4 = N * DD / 4;
    const int stride = NBLK_E * WPB * 2;

    convert_idx_kernel<<<(E + 255) / 256, 256>>>(ei, E);
    x_to_half_kernel<<<(total4 + 255) / 256, 256>>>(x, total4);
    prep_w1_kernel<<<128, 256>>>(W1);
    dim3 ggrid((N + 127) / 128, 4);
    node_gemm_mma_kernel<<<ggrid, 256>>>(N);
    edge_stats_kernel<<<NBLK_E, TPB_E>>>(E, stride);
    reduce_finalize_kernel<<<128, 256>>>(gamma, beta, 1.0f / (float)E);
    edge_out_kernel<<<NBLK_E, TPB_E>>>(W2, b2, (float*)d_out, E, stride);
}

// round 8
// speedup vs baseline: 1.4747x; 1.0809x over previous
#include <cuda_runtime.h>
#include <cuda_fp16.h>
#include <mma.h>
using namespace nvcuda;

#define DD 128
#define MAXN 100000
#define MAXE 1000000
#define NBLK_E 1184
#define TPB_E 256
#define WPB 8
#define BN_EPS 1e-5f

// ---------------- device scratch (no allocation allowed) ----------------
__device__ __half g_u[MAXN * DD];                // node proj, u-half (25.6 MB)
__device__ __half g_v[MAXN * DD];                // node proj, v-half (25.6 MB)
__device__ __half g_xh[MAXN * DD];               // x in fp16 (25.6 MB)
__device__ __half g_w1h[128 * 256];              // W1 fused [k][out] fp16
__device__ int2  g_ei32[MAXE];                   // edge index as int32 (8 MB)
__device__ float g_part[256 * NBLK_E];           // transposed partials [feat][block]
__device__ float g_a[DD];                        // BN scale
__device__ float g_c[DD];                        // BN shift

// ---------------- merged prep: idx->int32 | x->fp16 | W1 pack -----------
// grid: [0, xb) x-convert, [xb, xb+128) w1 pack, [xb+128, xb+128+eb) idx
__global__ __launch_bounds__(256) void prep_kernel(
    const float* __restrict__ x, const float* __restrict__ W1,
    const long long* __restrict__ ei, int total4, int E, int xb) {
    const int b = blockIdx.x;
    const int t = threadIdx.x;
    if (b < xb) {
        int i = b * 256 + t;
        if (i < total4) {
            float4 f = ((const float4*)x)[i];
            __half2 a = __floats2half2_rn(f.x, f.y);
            __half2 bb = __floats2half2_rn(f.z, f.w);
            uint2 o;
            o.x = *(unsigned int*)&a;
            o.y = *(unsigned int*)&bb;
            ((uint2*)g_xh)[i] = o;
        }
    } else if (b < xb + 128) {
        int idx = (b - xb) * 256 + t;
        int k = idx >> 8, o = idx & 255;
        float val = (o < 128) ? W1[o * 256 + k] : W1[(o - 128) * 256 + 128 + k];
        g_w1h[k * 256 + o] = __float2half(val);
    } else {
        // int64 edge_index (values < 2^31) has zero high dwords
        const int* eiv = (const int*)ei;
        int z = 0;
#pragma unroll
        for (int i = 0; i < 16; i++) z |= eiv[2 * i + 1];
        const bool is64 = (z == 0);
        int e = (b - xb - 128) * 256 + t;
        if (e < E) {
            int2 o;
            if (is64) {
                longlong2 p = ((const longlong2*)ei)[e];
                o = make_int2((int)p.x, (int)p.y);
            } else {
                o = ((const int2*)ei)[e];
            }
            g_ei32[e] = o;
        }
    }
}

// ---------------- node GEMM (wmma fp16, fp32 accum), warp tile 32x64 ----
// Block: 128 nodes x 128 feats. 8 warps = 4(node) x 2(feat).
// grid.y = 2: fblk 0 -> g_u, fblk 1 -> g_v. K chunked by 64.
#define A_LD 72
#define B_LD 136
#define S_LD 68
__global__ __launch_bounds__(256) void node_gemm_mma_kernel(int N) {
    __shared__ char raw[36864];
    __half (*As)[A_LD] = (__half(*)[A_LD])raw;                    // [128][72]
    __half (*Bs)[B_LD] = (__half(*)[B_LD])(raw + 128 * A_LD * 2); // [64][136]

    const int tid = threadIdx.x;
    const int warp = tid >> 5;
    const int lane = tid & 31;
    const int base = blockIdx.x * 128;
    const int fblk = blockIdx.y;                 // 0: u, 1: v
    const int wr = warp >> 1;                    // node row 0..3 (32 each)
    const int wc = warp & 1;                     // feat col 0..1 (64 each)
    const int fbase = fblk * 128;

    wmma::fragment<wmma::accumulator, 16, 16, 16, float> acc[2][4];
#pragma unroll
    for (int r = 0; r < 2; r++)
#pragma unroll
        for (int c = 0; c < 4; c++) wmma::fill_fragment(acc[r][c], 0.f);

    for (int kc = 0; kc < 128; kc += 64) {
        __syncthreads();
        // A tile: 128 nodes x 64 k  (2048 uint2)
#pragma unroll
        for (int it = 0; it < 8; it++) {
            int idx = it * 256 + tid;
            int r = idx >> 4;                    // 16 uint2 per row
            int c4 = idx & 15;
            int node = base + r;
            uint2 val = (node < N) ? ((const uint2*)&g_xh[node * 128 + kc])[c4]
                                   : make_uint2(0u, 0u);
            *(uint2*)&As[r][c4 * 4] = val;
        }
        // B tile: 64 k x 128 feats (2048 uint2)
#pragma unroll
        for (int it = 0; it < 8; it++) {
            int idx = it * 256 + tid;
            int r = idx >> 5;                    // 32 uint2 per row
            int c4 = idx & 31;
            uint2 val = ((const uint2*)&g_w1h[(kc + r) * 256 + fbase])[c4];
            *(uint2*)&Bs[r][c4 * 4] = val;
        }
        __syncthreads();
#pragma unroll
        for (int ks = 0; ks < 64; ks += 16) {
            wmma::fragment<wmma::matrix_a, 16, 16, 16, __half, wmma::row_major> af[2];
            wmma::fragment<wmma::matrix_b, 16, 16, 16, __half, wmma::row_major> bf[4];
            wmma::load_matrix_sync(af[0], &As[wr * 32][ks], A_LD);
            wmma::load_matrix_sync(af[1], &As[wr * 32 + 16][ks], A_LD);
#pragma unroll
            for (int c = 0; c < 4; c++)
                wmma::load_matrix_sync(bf[c], &Bs[ks][wc * 64 + c * 16], B_LD);
#pragma unroll
            for (int r = 0; r < 2; r++)
#pragma unroll
                for (int c = 0; c < 4; c++)
                    wmma::mma_sync(acc[r][c], af[r], bf[c], acc[r][c]);
        }
    }

    // Epilogue: per 16-row slab, stage fp32 in smem, convert, write fp16
    __syncthreads();
    float (*stg)[S_LD] = (float(*)[S_LD])(raw + warp * 16 * S_LD * 4); // [16][68]
    __half* gdst = fblk ? g_v : g_u;
#pragma unroll
    for (int r = 0; r < 2; r++) {
#pragma unroll
        for (int c = 0; c < 4; c++)
            wmma::store_matrix_sync(&stg[0][c * 16], acc[r][c], S_LD,
                                    wmma::mem_row_major);
        __syncwarp();
        // 32 lanes cover 16 rows x 64 feats: lane -> row lane>>1, half (lane&1)*32
        const int row = lane >> 1;
        const int fo = (lane & 1) * 32;
        const int node = base + wr * 32 + r * 16 + row;
        if (node < N) {
            const float* srow = &stg[row][fo];
            __half* dst = &gdst[node * 128 + wc * 64 + fo];
#pragma unroll
            for (int cc = 0; cc < 32; cc += 8) {
                __half2 h0 = __floats2half2_rn(srow[cc + 0], srow[cc + 1]);
                __half2 h1 = __floats2half2_rn(srow[cc + 2], srow[cc + 3]);
                __half2 h2 = __floats2half2_rn(srow[cc + 4], srow[cc + 5]);
                __half2 h3 = __floats2half2_rn(srow[cc + 6], srow[cc + 7]);
                uint4 o;
                o.x = *(unsigned int*)&h0;
                o.y = *(unsigned int*)&h1;
                o.z = *(unsigned int*)&h2;
                o.w = *(unsigned int*)&h3;
                *(uint4*)&dst[cc] = o;
            }
        }
        __syncwarp();
    }
}

// ---------------- edge pass 1: stats. 16 lanes/edge, 2 edges/warp -------
__global__ __launch_bounds__(TPB_E) void edge_stats_kernel(int E, int stride) {
    const int lane = threadIdx.x & 31;
    const int hl = lane & 15;
    const int half = lane >> 4;
    const int wid = threadIdx.x >> 5;
    const int gw = blockIdx.x * WPB + wid;

    float s[8], q[8];
#pragma unroll
    for (int j = 0; j < 8; j++) { s[j] = 0.f; q[j] = 0.f; }

    const uint4* __restrict__ U = (const uint4*)g_u;
    const uint4* __restrict__ V = (const uint4*)g_v;
    const int4* __restrict__ EI = (const int4*)g_ei32;

#pragma unroll 4
    for (int it = gw * 2; it < E; it += stride) {
        int4 idx = EI[it >> 1];
        int src = half ? idx.z : idx.x;
        int dst = half ? idx.w : idx.y;
        uint4 ur = U[src * 16 + hl];
        uint4 vr = V[dst * 16 + hl];
        float2 u0 = __half22float2(*(__half2*)&ur.x);
        float2 u1 = __half22float2(*(__half2*)&ur.y);
        float2 u2 = __half22float2(*(__half2*)&ur.z);
        float2 u3 = __half22float2(*(__half2*)&ur.w);
        float2 v0 = __half22float2(*(__half2*)&vr.x);
        float2 v1 = __half22float2(*(__half2*)&vr.y);
        float2 v2 = __half22float2(*(__half2*)&vr.z);
        float2 v3 = __half22float2(*(__half2*)&vr.w);
        float w[8];
        w[0] = u0.x + v0.x; w[1] = u0.y + v0.y;
        w[2] = u1.x + v1.x; w[3] = u1.y + v1.y;
        w[4] = u2.x + v2.x; w[5] = u2.y + v2.y;
        w[6] = u3.x + v3.x; w[7] = u3.y + v3.y;
#pragma unroll
        for (int j = 0; j < 8; j++) {
            s[j] += w[j];
            q[j] = fmaf(w[j], w[j], q[j]);
        }
    }

    __shared__ float red[WPB * 256];
    float* r = red + wid * 256;
    if (half == 0) {
#pragma unroll
        for (int j = 0; j < 8; j++) { r[hl * 8 + j] = s[j]; r[128 + hl * 8 + j] = q[j]; }
    }
    __syncwarp();
    if (half == 1) {
#pragma unroll
        for (int j = 0; j < 8; j++) { r[hl * 8 + j] += s[j]; r[128 + hl * 8 + j] += q[j]; }
    }
    __syncthreads();
    int j = threadIdx.x;
    float t = 0.f;
#pragma unroll
    for (int w = 0; w < WPB; w++) t += red[w * 256 + j];
    g_part[j * NBLK_E + blockIdx.x] = t;
}

// ---------------- fused reduce + BN finalize: 128 blocks ----------------
__global__ __launch_bounds__(256) void reduce_finalize_kernel(
    const float* __restrict__ gamma, const float* __restrict__ beta,
    float invE) {
    const int j = blockIdx.x;
    const int t = threadIdx.x;
    float s = 0.f, q = 0.f;
    for (int b = t; b < NBLK_E; b += 256) {
        s += g_part[j * NBLK_E + b];
        q += g_part[(128 + j) * NBLK_E + b];
    }
    __shared__ float rs[256], rq[256];
    rs[t] = s; rq[t] = q;
    __syncthreads();
#pragma unroll
    for (int o = 128; o >= 32; o >>= 1) {
        if (t < o) { rs[t] += rs[t + o]; rq[t] += rq[t + o]; }
        __syncthreads();
    }
    if (t < 32) {
        float vs = rs[t], vq = rq[t];
#pragma unroll
        for (int o = 16; o > 0; o >>= 1) {
            vs += __shfl_xor_sync(0xFFFFFFFFu, vs, o);
            vq += __shfl_xor_sync(0xFFFFFFFFu, vq, o);
        }
        if (t == 0) {
            float mean = vs * invE;
            float var = fmaf(-mean, mean, vq * invE);
            float a = gamma[j] * rsqrtf(var + BN_EPS);
            g_a[j] = a;
            g_c[j] = fmaf(-a, mean, beta[j]);
        }
    }
}

// ---------------- edge pass 2: out. 16 lanes/edge, 2 edges/warp ---------
__global__ __launch_bounds__(TPB_E) void edge_out_kernel(
    const float* __restrict__ W2, const float* __restrict__ b2,
    float* __restrict__ out, int E, int stride) {
    const int lane = threadIdx.x & 31;
    const int hl = lane & 15;
    const int half = lane >> 4;
    const int gw = blockIdx.x * WPB + (threadIdx.x >> 5);

    float a[8], c[8], wa[8], wb[8];
    {
        float4 t0 = *(const float4*)&g_a[hl * 8];
        float4 t1 = *(const float4*)&g_a[hl * 8 + 4];
        a[0]=t0.x; a[1]=t0.y; a[2]=t0.z; a[3]=t0.w;
        a[4]=t1.x; a[5]=t1.y; a[6]=t1.z; a[7]=t1.w;
        t0 = *(const float4*)&g_c[hl * 8];
        t1 = *(const float4*)&g_c[hl * 8 + 4];
        c[0]=t0.x; c[1]=t0.y; c[2]=t0.z; c[3]=t0.w;
        c[4]=t1.x; c[5]=t1.y; c[6]=t1.z; c[7]=t1.w;
        t0 = *(const float4*)&W2[hl * 8];
        t1 = *(const float4*)&W2[hl * 8 + 4];
        wa[0]=t0.x; wa[1]=t0.y; wa[2]=t0.z; wa[3]=t0.w;
        wa[4]=t1.x; wa[5]=t1.y; wa[6]=t1.z; wa[7]=t1.w;
        t0 = *(const float4*)&W2[128 + hl * 8];
        t1 = *(const float4*)&W2[128 + hl * 8 + 4];
        wb[0]=t0.x; wb[1]=t0.y; wb[2]=t0.z; wb[3]=t0.w;
        wb[4]=t1.x; wb[5]=t1.y; wb[6]=t1.z; wb[7]=t1.w;
    }
    const float bz0 = b2[0], bz1 = b2[1];

    const uint4* __restrict__ U = (const uint4*)g_u;
    const uint4* __restrict__ V = (const uint4*)g_v;
    const int4* __restrict__ EI = (const int4*)g_ei32;

#pragma unroll 4
    for (int it = gw * 2; it < E; it += stride) {
        int4 idx = EI[it >> 1];
        int src = half ? idx.z : idx.x;
        int dst = half ? idx.w : idx.y;
        uint4 ur = U[src * 16 + hl];
        uint4 vr = V[dst * 16 + hl];
        float2 u0 = __half22float2(*(__half2*)&ur.x);
        float2 u1 = __half22float2(*(__half2*)&ur.y);
        float2 u2 = __half22float2(*(__half2*)&ur.z);
        float2 u3 = __half22float2(*(__half2*)&ur.w);
        float2 v0 = __half22float2(*(__half2*)&vr.x);
        float2 v1 = __half22float2(*(__half2*)&vr.y);
        float2 v2 = __half22float2(*(__half2*)&vr.z);
        float2 v3 = __half22float2(*(__half2*)&vr.w);
        float w[8];
        w[0] = u0.x + v0.x; w[1] = u0.y + v0.y;
        w[2] = u1.x + v1.x; w[3] = u1.y + v1.y;
        w[4] = u2.x + v2.x; w[5] = u2.y + v2.y;
        w[6] = u3.x + v3.x; w[7] = u3.y + v3.y;
        float p0 = 0.f, p1 = 0.f;
#pragma unroll
        for (int j = 0; j < 8; j++) {
            float rr = fmaxf(fmaf(a[j], w[j], c[j]), 0.f);
            p0 = fmaf(rr, wa[j], p0);
            p1 = fmaf(rr, wb[j], p1);
        }
#pragma unroll
        for (int o = 8; o > 0; o >>= 1) {
            p0 += __shfl_xor_sync(0xFFFFFFFFu, p0, o);
            p1 += __shfl_xor_sync(0xFFFFFFFFu, p1, o);
        }
        if (hl == 0)
            ((float2*)out)[it + half] = make_float2(p0 + bz0, p1 + bz1);
    }
}

// ---------------- launch ------------------------------------------------
extern "C" void kernel_launch(void* const* d_in, const int* in_sizes, int n_in,
                              void* d_out, int out_size) {
    const float* x = (const float*)d_in[0];
    const long long* ei = (const long long*)d_in[1];
    const float* W1 = (const float*)d_in[2];
    // d_in[3] = b1 : cancels inside BatchNorm, unused
    const float* gamma = (const float*)d_in[4];
    const float* beta = (const float*)d_in[5];
    const float* W2 = (const float*)d_in[6];
    const float* b2 = (const float*)d_in[7];

    const int N = in_sizes[0] / DD;
    const int E = in_sizes[1] / 2;
    const int total4 = N * DD / 4;
    const int stride = NBLK_E * WPB * 2;
    const int xb = (total4 + 255) / 256;
    const int eb = (E + 255) / 256;

    prep_kernel<<<xb + 128 + eb, 256>>>(x, W1, ei, total4, E, xb);
    dim3 ggrid((N + 127) / 128, 2);
    node_gemm_mma_kernel<<<ggrid, 256>>>(N);
    edge_stats_kernel<<<NBLK_E, TPB_E>>>(E, stride);
    reduce_finalize_kernel<<<128, 256>>>(gamma, beta, 1.0f / (float)E);
    edge_out_kernel<<<NBLK_E, TPB_E>>>(W2, b2, (float*)d_out, E, stride);
}

// round 9
// speedup vs baseline: 1.5351x; 1.0409x over previous
#include <cuda_runtime.h>
#include <cuda_fp16.h>
#include <mma.h>
using namespace nvcuda;

#define DD 128
#define MAXN 100000
#define MAXE 1000000
#define NBLK_E 1184
#define TPB_E 256
#define WPB 8
#define BN_EPS 1e-5f

// ---------------- device scratch (no allocation allowed) ----------------
__device__ __half g_u[MAXN * DD];                // node proj, u-half (25.6 MB)
__device__ __half g_v[MAXN * DD];                // node proj, v-half (25.6 MB)
__device__ __half g_w1h[128 * 256];              // W1 fused [k][out] fp16
__device__ int2  g_ei32[MAXE];                   // edge index as int32 (8 MB)
__device__ float g_part[256 * NBLK_E];           // transposed partials [feat][block]
__device__ float g_a[DD];                        // BN scale
__device__ float g_c[DD];                        // BN shift

// ---------------- prep: W1 pack | idx->int32 ----------------------------
// grid: [0,128) w1 pack, [128, 128+eb) idx convert
__global__ __launch_bounds__(256) void prep_kernel(
    const float* __restrict__ W1, const long long* __restrict__ ei, int E) {
    const int b = blockIdx.x;
    const int t = threadIdx.x;
    if (b < 128) {
        int idx = b * 256 + t;
        int k = idx >> 8, o = idx & 255;
        float val = (o < 128) ? W1[o * 256 + k] : W1[(o - 128) * 256 + 128 + k];
        g_w1h[k * 256 + o] = __float2half(val);
    } else {
        // int64 edge_index (values < 2^31) has zero high dwords
        const int* eiv = (const int*)ei;
        int z = 0;
#pragma unroll
        for (int i = 0; i < 16; i++) z |= eiv[2 * i + 1];
        const bool is64 = (z == 0);
        int e = (b - 128) * 256 + t;
        if (e < E) {
            int2 o;
            if (is64) {
                longlong2 p = ((const longlong2*)ei)[e];
                o = make_int2((int)p.x, (int)p.y);
            } else {
                o = ((const int2*)ei)[e];
            }
            g_ei32[e] = o;
        }
    }
}

// ---------------- node GEMM: A staged once (fp32 x -> fp16 smem) --------
// Block: 128 nodes, loops fblk {u,v}. 8 warps = 4(node) x 2(feat 64).
// smem: A[128][136] (34816 B) + B[64][136] (17408 B) = 52224 B dynamic.
// Epilogue reuses the B region (4 warps per phase).
#define A_LD 136
#define B_LD 136
#define S_LD 68
__global__ __launch_bounds__(256) void node_gemm_mma_kernel(
    const float* __restrict__ x, int N) {
    extern __shared__ char raw[];
    __half (*As)[A_LD] = (__half(*)[A_LD])raw;                 // [128][136]
    __half (*Bs)[B_LD] = (__half(*)[B_LD])(raw + 34816);       // [64][136]

    const int tid = threadIdx.x;
    const int warp = tid >> 5;
    const int lane = tid & 31;
    const int base = blockIdx.x * 128;
    const int wr = warp >> 1;                    // node row 0..3 (32 each)
    const int wc = warp & 1;                     // feat col 0..1 (64 each)

    // Stage full A: 128 nodes x 128 k, fp32 -> fp16 (4096 float4)
#pragma unroll
    for (int it = 0; it < 16; it++) {
        int idx = it * 256 + tid;
        int r = idx >> 5;                        // 32 float4 per row
        int c4 = idx & 31;
        int node = base + r;
        float4 f = (node < N) ? ((const float4*)x)[node * 32 + c4]
                              : make_float4(0.f, 0.f, 0.f, 0.f);
        __half2 h0 = __floats2half2_rn(f.x, f.y);
        __half2 h1 = __floats2half2_rn(f.z, f.w);
        uint2 o;
        o.x = *(unsigned int*)&h0;
        o.y = *(unsigned int*)&h1;
        *(uint2*)&As[r][c4 * 4] = o;
    }

    for (int fblk = 0; fblk < 2; fblk++) {
        wmma::fragment<wmma::accumulator, 16, 16, 16, float> acc[2][4];
#pragma unroll
        for (int r = 0; r < 2; r++)
#pragma unroll
            for (int c = 0; c < 4; c++) wmma::fill_fragment(acc[r][c], 0.f);

        for (int kc = 0; kc < 128; kc += 64) {
            __syncthreads();                     // A ready / Bs free
            // B chunk: 64 k x 128 feats (2048 uint2)
#pragma unroll
            for (int it = 0; it < 8; it++) {
                int idx = it * 256 + tid;
                int r = idx >> 5;                // 32 uint2 per row
                int c4 = idx & 31;
                uint2 val = ((const uint2*)&g_w1h[(kc + r) * 256 + fblk * 128])[c4];
                *(uint2*)&Bs[r][c4 * 4] = val;
            }
            __syncthreads();
#pragma unroll
            for (int ks = 0; ks < 64; ks += 16) {
                wmma::fragment<wmma::matrix_a, 16, 16, 16, __half, wmma::row_major> af[2];
                wmma::fragment<wmma::matrix_b, 16, 16, 16, __half, wmma::row_major> bf[4];
                wmma::load_matrix_sync(af[0], &As[wr * 32][kc + ks], A_LD);
                wmma::load_matrix_sync(af[1], &As[wr * 32 + 16][kc + ks], A_LD);
#pragma unroll
                for (int c = 0; c < 4; c++)
                    wmma::load_matrix_sync(bf[c], &Bs[ks][wc * 64 + c * 16], B_LD);
#pragma unroll
                for (int r = 0; r < 2; r++)
#pragma unroll
                    for (int c = 0; c < 4; c++)
                        wmma::mma_sync(acc[r][c], af[r], bf[c], acc[r][c]);
            }
        }

        // Epilogue into Bs region: 4 warps per phase (4 x 4352 B = 17408 B)
        __syncthreads();
        float (*stg)[S_LD] = (float(*)[S_LD])(raw + 34816 + (warp & 3) * 4352);
        __half* gdst = fblk ? g_v : g_u;
#pragma unroll
        for (int phase = 0; phase < 2; phase++) {
            if ((warp >> 2) == phase) {
#pragma unroll
                for (int r = 0; r < 2; r++) {
#pragma unroll
                    for (int c = 0; c < 4; c++)
                        wmma::store_matrix_sync(&stg[0][c * 16], acc[r][c], S_LD,
                                                wmma::mem_row_major);
                    __syncwarp();
                    const int row = lane >> 1;
                    const int fo = (lane & 1) * 32;
                    const int node = base + wr * 32 + r * 16 + row;
                    if (node < N) {
                        const float* srow = &stg[row][fo];
                        __half* dst = &gdst[node * 128 + wc * 64 + fo];
#pragma unroll
                        for (int cc = 0; cc < 32; cc += 8) {
                            __half2 h0 = __floats2half2_rn(srow[cc + 0], srow[cc + 1]);
                            __half2 h1 = __floats2half2_rn(srow[cc + 2], srow[cc + 3]);
                            __half2 h2 = __floats2half2_rn(srow[cc + 4], srow[cc + 5]);
                            __half2 h3 = __floats2half2_rn(srow[cc + 6], srow[cc + 7]);
                            uint4 o;
                            o.x = *(unsigned int*)&h0;
                            o.y = *(unsigned int*)&h1;
                            o.z = *(unsigned int*)&h2;
                            o.w = *(unsigned int*)&h3;
                            *(uint4*)&dst[cc] = o;
                        }
                    }
                    __syncwarp();
                }
            }
            __syncthreads();
        }
    }
}

// ---------------- edge pass 1: stats. 16 lanes/edge, 2 edges/warp -------
__global__ __launch_bounds__(TPB_E) void edge_stats_kernel(int E, int stride) {
    const int lane = threadIdx.x & 31;
    const int hl = lane & 15;
    const int half = lane >> 4;
    const int wid = threadIdx.x >> 5;
    const int gw = blockIdx.x * WPB + wid;

    float s[8], q[8];
#pragma unroll
    for (int j = 0; j < 8; j++) { s[j] = 0.f; q[j] = 0.f; }

    const uint4* __restrict__ U = (const uint4*)g_u;
    const uint4* __restrict__ V = (const uint4*)g_v;
    const int4* __restrict__ EI = (const int4*)g_ei32;

#pragma unroll 4
    for (int it = gw * 2; it < E; it += stride) {
        int4 idx = EI[it >> 1];
        int src = half ? idx.z : idx.x;
        int dst = half ? idx.w : idx.y;
        uint4 ur = U[src * 16 + hl];
        uint4 vr = V[dst * 16 + hl];
        float2 u0 = __half22float2(*(__half2*)&ur.x);
        float2 u1 = __half22float2(*(__half2*)&ur.y);
        float2 u2 = __half22float2(*(__half2*)&ur.z);
        float2 u3 = __half22float2(*(__half2*)&ur.w);
        float2 v0 = __half22float2(*(__half2*)&vr.x);
        float2 v1 = __half22float2(*(__half2*)&vr.y);
        float2 v2 = __half22float2(*(__half2*)&vr.z);
        float2 v3 = __half22float2(*(__half2*)&vr.w);
        float w[8];
        w[0] = u0.x + v0.x; w[1] = u0.y + v0.y;
        w[2] = u1.x + v1.x; w[3] = u1.y + v1.y;
        w[4] = u2.x + v2.x; w[5] = u2.y + v2.y;
        w[6] = u3.x + v3.x; w[7] = u3.y + v3.y;
#pragma unroll
        for (int j = 0; j < 8; j++) {
            s[j] += w[j];
            q[j] = fmaf(w[j], w[j], q[j]);
        }
    }

    __shared__ float red[WPB * 256];
    float* r = red + wid * 256;
    if (half == 0) {
#pragma unroll
        for (int j = 0; j < 8; j++) { r[hl * 8 + j] = s[j]; r[128 + hl * 8 + j] = q[j]; }
    }
    __syncwarp();
    if (half == 1) {
#pragma unroll
        for (int j = 0; j < 8; j++) { r[hl * 8 + j] += s[j]; r[128 + hl * 8 + j] += q[j]; }
    }
    __syncthreads();
    int j = threadIdx.x;
    float t = 0.f;
#pragma unroll
    for (int w = 0; w < WPB; w++) t += red[w * 256 + j];
    g_part[j * NBLK_E + blockIdx.x] = t;
}

// ---------------- fused reduce + BN finalize: 128 blocks ----------------
__global__ __launch_bounds__(256) void reduce_finalize_kernel(
    const float* __restrict__ gamma, const float* __restrict__ beta,
    float invE) {
    const int j = blockIdx.x;
    const int t = threadIdx.x;
    float s = 0.f, q = 0.f;
    for (int b = t; b < NBLK_E; b += 256) {
        s += g_part[j * NBLK_E + b];
        q += g_part[(128 + j) * NBLK_E + b];
    }
    __shared__ float rs[256], rq[256];
    rs[t] = s; rq[t] = q;
    __syncthreads();
#pragma unroll
    for (int o = 128; o >= 32; o >>= 1) {
        if (t < o) { rs[t] += rs[t + o]; rq[t] += rq[t + o]; }
        __syncthreads();
    }
    if (t < 32) {
        float vs = rs[t], vq = rq[t];
#pragma unroll
        for (int o = 16; o > 0; o >>= 1) {
            vs += __shfl_xor_sync(0xFFFFFFFFu, vs, o);
            vq += __shfl_xor_sync(0xFFFFFFFFu, vq, o);
        }
        if (t == 0) {
            float mean = vs * invE;
            float var = fmaf(-mean, mean, vq * invE);
            float a = gamma[j] * rsqrtf(var + BN_EPS);
            g_a[j] = a;
            g_c[j] = fmaf(-a, mean, beta[j]);
        }
    }
}

// ---------------- edge pass 2: out. 16 lanes/edge, 2 edges/warp ---------
__global__ __launch_bounds__(TPB_E) void edge_out_kernel(
    const float* __restrict__ W2, const float* __restrict__ b2,
    float* __restrict__ out, int E, int stride) {
    const int lane = threadIdx.x & 31;
    const int hl = lane & 15;
    const int half = lane >> 4;
    const int gw = blockIdx.x * WPB + (threadIdx.x >> 5);

    float a[8], c[8], wa[8], wb[8];
    {
        float4 t0 = *(const float4*)&g_a[hl * 8];
        float4 t1 = *(const float4*)&g_a[hl * 8 + 4];
        a[0]=t0.x; a[1]=t0.y; a[2]=t0.z; a[3]=t0.w;
        a[4]=t1.x; a[5]=t1.y; a[6]=t1.z; a[7]=t1.w;
        t0 = *(const float4*)&g_c[hl * 8];
        t1 = *(const float4*)&g_c[hl * 8 + 4];
        c[0]=t0.x; c[1]=t0.y; c[2]=t0.z; c[3]=t0.w;
        c[4]=t1.x; c[5]=t1.y; c[6]=t1.z; c[7]=t1.w;
        t0 = *(const float4*)&W2[hl * 8];
        t1 = *(const float4*)&W2[hl * 8 + 4];
        wa[0]=t0.x; wa[1]=t0.y; wa[2]=t0.z; wa[3]=t0.w;
        wa[4]=t1.x; wa[5]=t1.y; wa[6]=t1.z; wa[7]=t1.w;
        t0 = *(const float4*)&W2[128 + hl * 8];
        t1 = *(const float4*)&W2[128 + hl * 8 + 4];
        wb[0]=t0.x; wb[1]=t0.y; wb[2]=t0.z; wb[3]=t0.w;
        wb[4]=t1.x; wb[5]=t1.y; wb[6]=t1.z; wb[7]=t1.w;
    }
    const float bz0 = b2[0], bz1 = b2[1];

    const uint4* __restrict__ U = (const uint4*)g_u;
    const uint4* __restrict__ V = (const uint4*)g_v;
    const int4* __restrict__ EI = (const int4*)g_ei32;

#pragma unroll 4
    for (int it = gw * 2; it < E; it += stride) {
        int4 idx = EI[it >> 1];
        int src = half ? idx.z : idx.x;
        int dst = half ? idx.w : idx.y;
        uint4 ur = U[src * 16 + hl];
        uint4 vr = V[dst * 16 + hl];
        float2 u0 = __half22float2(*(__half2*)&ur.x);
        float2 u1 = __half22float2(*(__half2*)&ur.y);
        float2 u2 = __half22float2(*(__half2*)&ur.z);
        float2 u3 = __half22float2(*(__half2*)&ur.w);
        float2 v0 = __half22float2(*(__half2*)&vr.x);
        float2 v1 = __half22float2(*(__half2*)&vr.y);
        float2 v2 = __half22float2(*(__half2*)&vr.z);
        float2 v3 = __half22float2(*(__half2*)&vr.w);
        float w[8];
        w[0] = u0.x + v0.x; w[1] = u0.y + v0.y;
        w[2] = u1.x + v1.x; w[3] = u1.y + v1.y;
        w[4] = u2.x + v2.x; w[5] = u2.y + v2.y;
        w[6] = u3.x + v3.x; w[7] = u3.y + v3.y;
        float p0 = 0.f, p1 = 0.f;
#pragma unroll
        for (int j = 0; j < 8; j++) {
            float rr = fmaxf(fmaf(a[j], w[j], c[j]), 0.f);
            p0 = fmaf(rr, wa[j], p0);
            p1 = fmaf(rr, wb[j], p1);
        }
#pragma unroll
        for (int o = 8; o > 0; o >>= 1) {
            p0 += __shfl_xor_sync(0xFFFFFFFFu, p0, o);
            p1 += __shfl_xor_sync(0xFFFFFFFFu, p1, o);
        }
        if (hl == 0)
            ((float2*)out)[it + half] = make_float2(p0 + bz0, p1 + bz1);
    }
}

// ---------------- launch ------------------------------------------------
extern "C" void kernel_launch(void* const* d_in, const int* in_sizes, int n_in,
                              void* d_out, int out_size) {
    const float* x = (const float*)d_in[0];
    const long long* ei = (const long long*)d_in[1];
    const float* W1 = (const float*)d_in[2];
    // d_in[3] = b1 : cancels inside BatchNorm, unused
    const float* gamma = (const float*)d_in[4];
    const float* beta = (const float*)d_in[5];
    const float* W2 = (const float*)d_in[6];
    const float* b2 = (const float*)d_in[7];

    const int N = in_sizes[0] / DD;
    const int E = in_sizes[1] / 2;
    const int stride = NBLK_E * WPB * 2;
    const int eb = (E + 255) / 256;
    const int GEMM_SMEM = 52224;

    static int smem_set = 0;
    if (!smem_set) {
        cudaFuncSetAttribute(node_gemm_mma_kernel,
                             cudaFuncAttributeMaxDynamicSharedMemorySize, GEMM_SMEM);
        smem_set = 1;
    }

    prep_kernel<<<128 + eb, 256>>>(W1, ei, E);
    node_gemm_mma_kernel<<<(N + 127) / 128, 256, GEMM_SMEM>>>(x, N);
    edge_stats_kernel<<<NBLK_E, TPB_E>>>(E, stride);
    reduce_finalize_kernel<<<128, 256>>>(gamma, beta, 1.0f / (float)E);
    edge_out_kernel<<<NBLK_E, TPB_E>>>(W2, b2, (float*)d_out, E, stride);
}

// round 11
// speedup vs baseline: 1.5736x; 1.0251x over previous
#include <cuda_runtime.h>
#include <cuda_fp16.h>
#include <mma.h>
using namespace nvcuda;

#define DD 128
#define MAXN 100000
#define MAXE 1000000
#define NBLK_E 1184
#define TPB_E 256
#define WPB 8
#define BN_EPS 1e-5f

// ---------------- device scratch (no allocation allowed) ----------------
// +128 rows padding: gemm tail block stores full 16-row fragments
__device__ __half g_u[(MAXN + 128) * DD];        // node proj, u-half
__device__ __half g_v[(MAXN + 128) * DD];        // node proj, v-half
__device__ __half g_w1h[128 * 256];              // W1 fused [k][out] fp16
__device__ int2  g_ei32[MAXE];                   // edge index as int32 (8 MB)
__device__ float g_part[256 * NBLK_E];           // transposed partials [feat][block]
__device__ float g_a[DD];                        // BN scale
__device__ float g_c[DD];                        // BN shift

// ---------------- prep: W1 pack | idx->int32 ----------------------------
// grid: [0,128) w1 pack, [128, 128+eb) idx convert
__global__ __launch_bounds__(256) void prep_kernel(
    const float* __restrict__ W1, const long long* __restrict__ ei, int E) {
    const int b = blockIdx.x;
    const int t = threadIdx.x;
    if (b < 128) {
        int idx = b * 256 + t;
        int k = idx >> 8, o = idx & 255;
        float val = (o < 128) ? W1[o * 256 + k] : W1[(o - 128) * 256 + 128 + k];
        g_w1h[k * 256 + o] = __float2half(val);
    } else {
        // int64 edge_index (values < 2^31) has zero high dwords
        const int* eiv = (const int*)ei;
        int z = 0;
#pragma unroll
        for (int i = 0; i < 16; i++) z |= eiv[2 * i + 1];
        const bool is64 = (z == 0);
        int e = (b - 128) * 256 + t;
        if (e < E) {
            int2 o;
            if (is64) {
                longlong2 p = ((const longlong2*)ei)[e];
                o = make_int2((int)p.x, (int)p.y);
            } else {
                o = ((const int2*)ei)[e];
            }
            g_ei32[e] = o;
        }
    }
}

// ---------------- node GEMM: A staged once, fp16 accumulate -------------
// Block: 128 nodes, loops fblk {u,v}. 8 warps = 4(node) x 2(feat 64).
// smem: A[128][136] (34816 B) + B[64][136] (17408 B) = 52224 B dynamic.
// Epilogue: store_matrix_sync DIRECTLY to global fp16 (padding absorbs tail).
#define A_LD 136
#define B_LD 136
__global__ __launch_bounds__(256) void node_gemm_mma_kernel(
    const float* __restrict__ x, int N) {
    extern __shared__ char raw[];
    __half (*As)[A_LD] = (__half(*)[A_LD])raw;                 // [128][136]
    __half (*Bs)[B_LD] = (__half(*)[B_LD])(raw + 34816);       // [64][136]

    const int tid = threadIdx.x;
    const int warp = tid >> 5;
    const int base = blockIdx.x * 128;
    const int wr = warp >> 1;                    // node row 0..3 (32 each)
    const int wc = warp & 1;                     // feat col 0..1 (64 each)

    // Stage full A: 128 nodes x 128 k, fp32 -> fp16 (4096 float4)
#pragma unroll
    for (int it = 0; it < 16; it++) {
        int idx = it * 256 + tid;
        int r = idx >> 5;                        // 32 float4 per row
        int c4 = idx & 31;
        int node = base + r;
        float4 f = (node < N) ? ((const float4*)x)[node * 32 + c4]
                              : make_float4(0.f, 0.f, 0.f, 0.f);
        __half2 h0 = __floats2half2_rn(f.x, f.y);
        __half2 h1 = __floats2half2_rn(f.z, f.w);
        uint2 o;
        o.x = *(unsigned int*)&h0;
        o.y = *(unsigned int*)&h1;
        *(uint2*)&As[r][c4 * 4] = o;
    }

    for (int fblk = 0; fblk < 2; fblk++) {
        wmma::fragment<wmma::accumulator, 16, 16, 16, __half> acc[2][4];
#pragma unroll
        for (int r = 0; r < 2; r++)
#pragma unroll
            for (int c = 0; c < 4; c++)
                wmma::fill_fragment(acc[r][c], __float2half(0.f));

        for (int kc = 0; kc < 128; kc += 64) {
            __syncthreads();                     // A ready / Bs free
            // B chunk: 64 k x 128 feats (2048 uint2)
#pragma unroll
            for (int it = 0; it < 8; it++) {
                int idx = it * 256 + tid;
                int r = idx >> 5;                // 32 uint2 per row
                int c4 = idx & 31;
                uint2 val = ((const uint2*)&g_w1h[(kc + r) * 256 + fblk * 128])[c4];
                *(uint2*)&Bs[r][c4 * 4] = val;
            }
            __syncthreads();
#pragma unroll
            for (int ks = 0; ks < 64; ks += 16) {
                wmma::fragment<wmma::matrix_a, 16, 16, 16, __half, wmma::row_major> af[2];
                wmma::fragment<wmma::matrix_b, 16, 16, 16, __half, wmma::row_major> bf[4];
                wmma::load_matrix_sync(af[0], &As[wr * 32][kc + ks], A_LD);
                wmma::load_matrix_sync(af[1], &As[wr * 32 + 16][kc + ks], A_LD);
#pragma unroll
                for (int c = 0; c < 4; c++)
                    wmma::load_matrix_sync(bf[c], &Bs[ks][wc * 64 + c * 16], B_LD);
#pragma unroll
                for (int r = 0; r < 2; r++)
#pragma unroll
                    for (int c = 0; c < 4; c++)
                        wmma::mma_sync(acc[r][c], af[r], bf[c], acc[r][c]);
            }
        }

        // Epilogue: direct fp16 store to global (padded arrays absorb tail)
        __half* gdst = fblk ? g_v : g_u;
#pragma unroll
        for (int r = 0; r < 2; r++)
#pragma unroll
            for (int c = 0; c < 4; c++)
                wmma::store_matrix_sync(
                    &gdst[(unsigned)(base + wr * 32 + r * 16) * 128 + wc * 64 + c * 16],
                    acc[r][c], 128, wmma::mem_row_major);
    }
}

// ---------------- edge pass 1: stats. 16 lanes/edge, 2 edges/warp -------
__global__ __launch_bounds__(TPB_E) void edge_stats_kernel(int E, int stride) {
    const int lane = threadIdx.x & 31;
    const int hl = lane & 15;
    const int half = lane >> 4;
    const int wid = threadIdx.x >> 5;
    const int gw = blockIdx.x * WPB + wid;

    float s[8], q[8];
#pragma unroll
    for (int j = 0; j < 8; j++) { s[j] = 0.f; q[j] = 0.f; }

    const uint4* __restrict__ U = (const uint4*)g_u;
    const uint4* __restrict__ V = (const uint4*)g_v;
    const int4* __restrict__ EI = (const int4*)g_ei32;

#pragma unroll 4
    for (int it = gw * 2; it < E; it += stride) {
        int4 idx = EI[it >> 1];
        int src = half ? idx.z : idx.x;
        int dst = half ? idx.w : idx.y;
        uint4 ur = U[src * 16 + hl];
        uint4 vr = V[dst * 16 + hl];
        float2 u0 = __half22float2(*(__half2*)&ur.x);
        float2 u1 = __half22float2(*(__half2*)&ur.y);
        float2 u2 = __half22float2(*(__half2*)&ur.z);
        float2 u3 = __half22float2(*(__half2*)&ur.w);
        float2 v0 = __half22float2(*(__half2*)&vr.x);
        float2 v1 = __half22float2(*(__half2*)&vr.y);
        float2 v2 = __half22float2(*(__half2*)&vr.z);
        float2 v3 = __half22float2(*(__half2*)&vr.w);
        float w[8];
        w[0] = u0.x + v0.x; w[1] = u0.y + v0.y;
        w[2] = u1.x + v1.x; w[3] = u1.y + v1.y;
        w[4] = u2.x + v2.x; w[5] = u2.y + v2.y;
        w[6] = u3.x + v3.x; w[7] = u3.y + v3.y;
#pragma unroll
        for (int j = 0; j < 8; j++) {
            s[j] += w[j];
            q[j] = fmaf(w[j], w[j], q[j]);
        }
    }

    __shared__ float red[WPB * 256];
    float* r = red + wid * 256;
    if (half == 0) {
#pragma unroll
        for (int j = 0; j < 8; j++) { r[hl * 8 + j] = s[j]; r[128 + hl * 8 + j] = q[j]; }
    }
    __syncwarp();
    if (half == 1) {
#pragma unroll
        for (int j = 0; j < 8; j++) { r[hl * 8 + j] += s[j]; r[128 + hl * 8 + j] += q[j]; }
    }
    __syncthreads();
    int j = threadIdx.x;
    float t = 0.f;
#pragma unroll
    for (int w = 0; w < WPB; w++) t += red[w * 256 + j];
    g_part[j * NBLK_E + blockIdx.x] = t;
}

// ---------------- fused reduce + BN finalize: 128 blocks ----------------
__global__ __launch_bounds__(256) void reduce_finalize_kernel(
    const float* __restrict__ gamma, const float* __restrict__ beta,
    float invE) {
    const int j = blockIdx.x;
    const int t = threadIdx.x;
    float s = 0.f, q = 0.f;
    for (int b = t; b < NBLK_E; b += 256) {
        s += g_part[j * NBLK_E + b];
        q += g_part[(128 + j) * NBLK_E + b];
    }
    __shared__ float rs[256], rq[256];
    rs[t] = s; rq[t] = q;
    __syncthreads();
#pragma unroll
    for (int o = 128; o >= 32; o >>= 1) {
        if (t < o) { rs[t] += rs[t + o]; rq[t] += rq[t + o]; }
        __syncthreads();
    }
    if (t < 32) {
        float vs = rs[t], vq = rq[t];
#pragma unroll
        for (int o = 16; o > 0; o >>= 1) {
            vs += __shfl_xor_sync(0xFFFFFFFFu, vs, o);
            vq += __shfl_xor_sync(0xFFFFFFFFu, vq, o);
        }
        if (t == 0) {
            float mean = vs * invE;
            float var = fmaf(-mean, mean, vq * invE);
            float a = gamma[j] * rsqrtf(var + BN_EPS);
            g_a[j] = a;
            g_c[j] = fmaf(-a, mean, beta[j]);
        }
    }
}

// ---------------- edge pass 2: out. 16 lanes/edge, 2 edges/warp ---------
__global__ __launch_bounds__(TPB_E) void edge_out_kernel(
    const float* __restrict__ W2, const float* __restrict__ b2,
    float* __restrict__ out, int E, int stride) {
    const int lane = threadIdx.x & 31;
    const int hl = lane & 15;
    const int half = lane >> 4;
    const int gw = blockIdx.x * WPB + (threadIdx.x >> 5);

    float a[8], c[8], wa[8], wb[8];
    {
        float4 t0 = *(const float4*)&g_a[hl * 8];
        float4 t1 = *(const float4*)&g_a[hl * 8 + 4];
        a[0]=t0.x; a[1]=t0.y; a[2]=t0.z; a[3]=t0.w;
        a[4]=t1.x; a[5]=t1.y; a[6]=t1.z; a[7]=t1.w;
        t0 = *(const float4*)&g_c[hl * 8];
        t1 = *(const float4*)&g_c[hl * 8 + 4];
        c[0]=t0.x; c[1]=t0.y; c[2]=t0.z; c[3]=t0.w;
        c[4]=t1.x; c[5]=t1.y; c[6]=t1.z; c[7]=t1.w;
        t0 = *(const float4*)&W2[hl * 8];
        t1 = *(const float4*)&W2[hl * 8 + 4];
        wa[0]=t0.x; wa[1]=t0.y; wa[2]=t0.z; wa[3]=t0.w;
        wa[4]=t1.x; wa[5]=t1.y; wa[6]=t1.z; wa[7]=t1.w;
        t0 = *(const float4*)&W2[128 + hl * 8];
        t1 = *(const float4*)&W2[128 + hl * 8 + 4];
        wb[0]=t0.x; wb[1]=t0.y; wb[2]=t0.z; wb[3]=t0.w;
        wb[4]=t1.x; wb[5]=t1.y; wb[6]=t1.z; wb[7]=t1.w;
    }
    const float bz0 = b2[0], bz1 = b2[1];

    const uint4* __restrict__ U = (const uint4*)g_u;
    const uint4* __restrict__ V = (const uint4*)g_v;
    const int4* __restrict__ EI = (const int4*)g_ei32;

#pragma unroll 4
    for (int it = gw * 2; it < E; it += stride) {
        int4 idx = EI[it >> 1];
        int src = half ? idx.z : idx.x;
        int dst = half ? idx.w : idx.y;
        uint4 ur = U[src * 16 + hl];
        uint4 vr = V[dst * 16 + hl];
        float2 u0 = __half22float2(*(__half2*)&ur.x);
        float2 u1 = __half22float2(*(__half2*)&ur.y);
        float2 u2 = __half22float2(*(__half2*)&ur.z);
        float2 u3 = __half22float2(*(__half2*)&ur.w);
        float2 v0 = __half22float2(*(__half2*)&vr.x);
        float2 v1 = __half22float2(*(__half2*)&vr.y);
        float2 v2 = __half22float2(*(__half2*)&vr.z);
        float2 v3 = __half22float2(*(__half2*)&vr.w);
        float w[8];
        w[0] = u0.x + v0.x; w[1] = u0.y + v0.y;
        w[2] = u1.x + v1.x; w[3] = u1.y + v1.y;
        w[4] = u2.x + v2.x; w[5] = u2.y + v2.y;
        w[6] = u3.x + v3.x; w[7] = u3.y + v3.y;
        float p0 = 0.f, p1 = 0.f;
#pragma unroll
        for (int j = 0; j < 8; j++) {
            float rr = fmaxf(fmaf(a[j], w[j], c[j]), 0.f);
            p0 = fmaf(rr, wa[j], p0);
            p1 = fmaf(rr, wb[j], p1);
        }
#pragma unroll
        for (int o = 8; o > 0; o >>= 1) {
            p0 += __shfl_xor_sync(0xFFFFFFFFu, p0, o);
            p1 += __shfl_xor_sync(0xFFFFFFFFu, p1, o);
        }
        if (hl == 0)
            ((float2*)out)[it + half] = make_float2(p0 + bz0, p1 + bz1);
    }
}

// ---------------- launch ------------------------------------------------
extern "C" void kernel_launch(void* const* d_in, const int* in_sizes, int n_in,
                              void* d_out, int out_size) {
    const float* x = (const float*)d_in[0];
    const long long* ei = (const long long*)d_in[1];
    const float* W1 = (const float*)d_in[2];
    // d_in[3] = b1 : cancels inside BatchNorm, unused
    const float* gamma = (const float*)d_in[4];
    const float* beta = (const float*)d_in[5];
    const float* W2 = (const float*)d_in[6];
    const float* b2 = (const float*)d_in[7];

    const int N = in_sizes[0] / DD;
    const int E = in_sizes[1] / 2;
    const int stride = NBLK_E * WPB * 2;
    const int eb = (E + 255) / 256;
    const int GEMM_SMEM = 52224;

    static int smem_set = 0;
    if (!smem_set) {
        cudaFuncSetAttribute(node_gemm_mma_kernel,
                             cudaFuncAttributeMaxDynamicSharedMemorySize, GEMM_SMEM);
        smem_set = 1;
    }

    prep_kernel<<<128 + eb, 256>>>(W1, ei, E);
    node_gemm_mma_kernel<<<(N + 127) / 128, 256, GEMM_SMEM>>>(x, N);
    edge_stats_kernel<<<NBLK_E, TPB_E>>>(E, stride);
    reduce_finalize_kernel<<<128, 256>>>(gamma, beta, 1.0f / (float)E);
    edge_out_kernel<<<NBLK_E, TPB_E>>>(W2, b2, (float*)d_out, E, stride);
}

// round 12
// speedup vs baseline: 1.6092x; 1.0226x over previous
#include <cuda_runtime.h>
#include <cuda_fp16.h>
#include <cstdint>

#define DD 128
#define MAXN 100000
#define MAXE 1000000
#define NBLK_E 1184
#define TPB_E 256
#define WPB 8
#define BN_EPS 1e-5f

// ---------------- device scratch (no allocation allowed) ----------------
// +128 rows padding: gemm tail block stores full 16-row fragments
__device__ __half g_u[(MAXN + 128) * DD];        // node proj, u-half
__device__ __half g_v[(MAXN + 128) * DD];        // node proj, v-half
__device__ __align__(16) __half g_w1f[8 * 32 * 32 * 4]; // W1 in B-fragment layout
__device__ int2  g_ei32[MAXE];                   // edge index as int32 (8 MB)
__device__ float g_part[256 * NBLK_E];           // transposed partials [feat][block]
__device__ float g_a[DD];                        // BN scale
__device__ float g_c[DD];                        // BN shift

__device__ __forceinline__ uint32_t smem_u32(const void* p) {
    uint32_t a;
    asm("{ .reg .u64 t; cvta.to.shared.u64 t, %1; cvt.u32.u64 %0, t; }"
        : "=r"(a) : "l"(p));
    return a;
}

// ---------------- prep: W1 -> mma B-fragment layout | idx->int32 --------
// B frag (m16n8k16, col): lane l holds k={2c,2c+1,2c+8,2c+9}, n=l/4, c=l%4.
__global__ __launch_bounds__(256) void prep_kernel(
    const float* __restrict__ W1, const long long* __restrict__ ei, int E) {
    const int b = blockIdx.x;
    const int t = threadIdx.x;
    if (b < 128) {
        int idx = b * 256 + t;                   // 0..32767
        int o = idx >> 7, k = idx & 127;         // o: fused out 0..255, k: 0..127
        float val = (o < 128) ? W1[o * 256 + k] : W1[(o - 128) * 256 + 128 + k];
        int kt = k >> 4, k_in = k & 15;
        int ot = o >> 3, n_in = o & 7;
        int l = n_in * 4 + ((k_in & 7) >> 1);
        int slot = ((k_in >> 3) << 1) | (k_in & 1);
        g_w1f[(((kt * 32 + ot) * 32 + l) << 2) + slot] = __float2half(val);
    } else {
        // int64 edge_index (values < 2^31) has zero high dwords
        const int* eiv = (const int*)ei;
        int z = 0;
#pragma unroll
        for (int i = 0; i < 16; i++) z |= eiv[2 * i + 1];
        const bool is64 = (z == 0);
        int e = (b - 128) * 256 + t;
        if (e < E) {
            int2 o;
            if (is64) {
                longlong2 p = ((const longlong2*)ei)[e];
                o = make_int2((int)p.x, (int)p.y);
            } else {
                o = ((const int2*)ei)[e];
            }
            g_ei32[e] = o;
        }
    }
}

// ---------------- node GEMM: raw mma.sync, B frags direct from global ---
// Block: 128 nodes x 256 out. 8 warps = 4(node rows of 32) x 2(out cols of 64).
// A: smem [128][136] fp16, ldmatrix.x4. B: coalesced LDG.64 from g_w1f.
// Acc fp16 in regs (both u/v halves live). Epilogue: direct half2 stores.
#define A_LD 136
#define GEMM_SMEM 34816
__global__ __launch_bounds__(256) void node_gemm_mma_kernel(
    const float* __restrict__ x, int N) {
    extern __shared__ char raw[];
    __half (*As)[A_LD] = (__half(*)[A_LD])raw;   // [128][136]

    const int tid = threadIdx.x;
    const int warp = tid >> 5;
    const int lane = tid & 31;
    const int base = blockIdx.x * 128;
    const int wr = warp >> 1;                    // node row group (32 rows)
    const int wc = warp & 1;                     // out col group (64 cols)

    // Stage A: 128 nodes x 128 k, fp32 -> fp16 (4096 float4)
#pragma unroll
    for (int it = 0; it < 16; it++) {
        int idx = it * 256 + tid;
        int r = idx >> 5;
        int c4 = idx & 31;
        int node = base + r;
        float4 f = (node < N) ? ((const float4*)x)[node * 32 + c4]
                              : make_float4(0.f, 0.f, 0.f, 0.f);
        __half2 h0 = __floats2half2_rn(f.x, f.y);
        __half2 h1 = __floats2half2_rn(f.z, f.w);
        uint2 o;
        o.x = *(unsigned int*)&h0;
        o.y = *(unsigned int*)&h1;
        *(uint2*)&As[r][c4 * 4] = o;
    }
    __syncthreads();

    // acc[mt][fblk][nt][2] fp16x2 regs, zeroed
    uint32_t acc[2][2][8][2];
#pragma unroll
    for (int mt = 0; mt < 2; mt++)
#pragma unroll
        for (int fb = 0; fb < 2; fb++)
#pragma unroll
            for (int nt = 0; nt < 8; nt++) {
                acc[mt][fb][nt][0] = 0u;
                acc[mt][fb][nt][1] = 0u;
            }

    // Per-lane ldmatrix row pointer (A m16k16 via m8n8.x4):
    // lane l -> row (l&15), k-half (l>>4)*8
    const uint32_t a_base = smem_u32(raw);
    const uint32_t rowptr = a_base +
        ((uint32_t)((wr * 32 + (lane & 15)) * A_LD + ((lane >> 4) << 3)) << 1);

    const uint2* __restrict__ Wf = (const uint2*)g_w1f;
    const int ot_base0 = wc * 8;                 // fblk 0: ot 0..15 range
#pragma unroll
    for (int kt = 0; kt < 8; kt++) {
        // A fragments: 2 x ldmatrix.x4
        uint32_t a[2][4];
#pragma unroll
        for (int mt = 0; mt < 2; mt++) {
            uint32_t addr = rowptr + (uint32_t)(mt * 16 * A_LD * 2 + kt * 32);
            asm volatile(
                "ldmatrix.sync.aligned.m8n8.x4.shared.b16 {%0,%1,%2,%3}, [%4];"
                : "=r"(a[mt][0]), "=r"(a[mt][1]), "=r"(a[mt][2]), "=r"(a[mt][3])
                : "r"(addr));
        }
        // B fragments: coalesced LDG.64 (frag (kt, ot), ot = fb*16 + wc*8 + nt)
        uint2 bfr[2][8];
#pragma unroll
        for (int fb = 0; fb < 2; fb++)
#pragma unroll
            for (int nt = 0; nt < 8; nt++)
                bfr[fb][nt] = Wf[((kt * 32 + fb * 16 + ot_base0 + nt) << 5) + lane];
        // MMA
#pragma unroll
        for (int mt = 0; mt < 2; mt++)
#pragma unroll
            for (int fb = 0; fb < 2; fb++)
#pragma unroll
                for (int nt = 0; nt < 8; nt++)
                    asm volatile(
                        "mma.sync.aligned.m16n8k16.row.col.f16.f16.f16.f16 "
                        "{%0,%1}, {%2,%3,%4,%5}, {%6,%7}, {%0,%1};"
                        : "+r"(acc[mt][fb][nt][0]), "+r"(acc[mt][fb][nt][1])
                        : "r"(a[mt][0]), "r"(a[mt][1]), "r"(a[mt][2]), "r"(a[mt][3]),
                          "r"(bfr[fb][nt].x), "r"(bfr[fb][nt].y));
    }

    // Epilogue: acc lane layout: c0c1 row l/4 col 2(l%4)+{0,1}; c2c3 row +8.
    const int row0 = base + wr * 32 + (lane >> 2);
    const int col0 = wc * 64 + ((lane & 3) << 1);
#pragma unroll
    for (int fb = 0; fb < 2; fb++) {
        __half* dst = fb ? g_v : g_u;
#pragma unroll
        for (int mt = 0; mt < 2; mt++)
#pragma unroll
            for (int nt = 0; nt < 8; nt++) {
                int r = row0 + mt * 16;
                int cc = col0 + nt * 8;
                *(uint32_t*)&dst[(unsigned)r * 128 + cc] = acc[mt][fb][nt][0];
                *(uint32_t*)&dst[(unsigned)(r + 8) * 128 + cc] = acc[mt][fb][nt][1];
            }
    }
}

// ---------------- edge pass 1: stats. 16 lanes/edge, 2 edges/warp -------
__global__ __launch_bounds__(TPB_E) void edge_stats_kernel(int E, int stride) {
    const int lane = threadIdx.x & 31;
    const int hl = lane & 15;
    const int half = lane >> 4;
    const int wid = threadIdx.x >> 5;
    const int gw = blockIdx.x * WPB + wid;

    float s[8], q[8];
#pragma unroll
    for (int j = 0; j < 8; j++) { s[j] = 0.f; q[j] = 0.f; }

    const uint4* __restrict__ U = (const uint4*)g_u;
    const uint4* __restrict__ V = (const uint4*)g_v;
    const int4* __restrict__ EI = (const int4*)g_ei32;

#pragma unroll 4
    for (int it = gw * 2; it < E; it += stride) {
        int4 idx = EI[it >> 1];
        int src = half ? idx.z : idx.x;
        int dst = half ? idx.w : idx.y;
        uint4 ur = U[src * 16 + hl];
        uint4 vr = V[dst * 16 + hl];
        float2 u0 = __half22float2(*(__half2*)&ur.x);
        float2 u1 = __half22float2(*(__half2*)&ur.y);
        float2 u2 = __half22float2(*(__half2*)&ur.z);
        float2 u3 = __half22float2(*(__half2*)&ur.w);
        float2 v0 = __half22float2(*(__half2*)&vr.x);
        float2 v1 = __half22float2(*(__half2*)&vr.y);
        float2 v2 = __half22float2(*(__half2*)&vr.z);
        float2 v3 = __half22float2(*(__half2*)&vr.w);
        float w[8];
        w[0] = u0.x + v0.x; w[1] = u0.y + v0.y;
        w[2] = u1.x + v1.x; w[3] = u1.y + v1.y;
        w[4] = u2.x + v2.x; w[5] = u2.y + v2.y;
        w[6] = u3.x + v3.x; w[7] = u3.y + v3.y;
#pragma unroll
        for (int j = 0; j < 8; j++) {
            s[j] += w[j];
            q[j] = fmaf(w[j], w[j], q[j]);
        }
    }

    __shared__ float red[WPB * 256];
    float* r = red + wid * 256;
    if (half == 0) {
#pragma unroll
        for (int j = 0; j < 8; j++) { r[hl * 8 + j] = s[j]; r[128 + hl * 8 + j] = q[j]; }
    }
    __syncwarp();
    if (half == 1) {
#pragma unroll
        for (int j = 0; j < 8; j++) { r[hl * 8 + j] += s[j]; r[128 + hl * 8 + j] += q[j]; }
    }
    __syncthreads();
    int j = threadIdx.x;
    float t = 0.f;
#pragma unroll
    for (int w = 0; w < WPB; w++) t += red[w * 256 + j];
    g_part[j * NBLK_E + blockIdx.x] = t;
}

// ---------------- fused reduce + BN finalize: 128 blocks ----------------
__global__ __launch_bounds__(256) void reduce_finalize_kernel(
    const float* __restrict__ gamma, const float* __restrict__ beta,
    float invE) {
    const int j = blockIdx.x;
    const int t = threadIdx.x;
    float s = 0.f, q = 0.f;
    for (int b = t; b < NBLK_E; b += 256) {
        s += g_part[j * NBLK_E + b];
        q += g_part[(128 + j) * NBLK_E + b];
    }
    __shared__ float rs[256], rq[256];
    rs[t] = s; rq[t] = q;
    __syncthreads();
#pragma unroll
    for (int o = 128; o >= 32; o >>= 1) {
        if (t < o) { rs[t] += rs[t + o]; rq[t] += rq[t + o]; }
        __syncthreads();
    }
    if (t < 32) {
        float vs = rs[t], vq = rq[t];
#pragma unroll
        for (int o = 16; o > 0; o >>= 1) {
            vs += __shfl_xor_sync(0xFFFFFFFFu, vs, o);
            vq += __shfl_xor_sync(0xFFFFFFFFu, vq, o);
        }
        if (t == 0) {
            float mean = vs * invE;
            float var = fmaf(-mean, mean, vq * invE);
            float a = gamma[j] * rsqrtf(var + BN_EPS);
            g_a[j] = a;
            g_c[j] = fmaf(-a, mean, beta[j]);
        }
    }
}

// ---------------- edge pass 2: out. 16 lanes/edge, 2 edges/warp ---------
__global__ __launch_bounds__(TPB_E) void edge_out_kernel(
    const float* __restrict__ W2, const float* __restrict__ b2,
    float* __restrict__ out, int E, int stride) {
    const int lane = threadIdx.x & 31;
    const int hl = lane & 15;
    const int half = lane >> 4;
    const int gw = blockIdx.x * WPB + (threadIdx.x >> 5);

    float a[8], c[8], wa[8], wb[8];
    {
        float4 t0 = *(const float4*)&g_a[hl * 8];
        float4 t1 = *(const float4*)&g_a[hl * 8 + 4];
        a[0]=t0.x; a[1]=t0.y; a[2]=t0.z; a[3]=t0.w;
        a[4]=t1.x; a[5]=t1.y; a[6]=t1.z; a[7]=t1.w;
        t0 = *(const float4*)&g_c[hl * 8];
        t1 = *(const float4*)&g_c[hl * 8 + 4];
        c[0]=t0.x; c[1]=t0.y; c[2]=t0.z; c[3]=t0.w;
        c[4]=t1.x; c[5]=t1.y; c[6]=t1.z; c[7]=t1.w;
        t0 = *(const float4*)&W2[hl * 8];
        t1 = *(const float4*)&W2[hl * 8 + 4];
        wa[0]=t0.x; wa[1]=t0.y; wa[2]=t0.z; wa[3]=t0.w;
        wa[4]=t1.x; wa[5]=t1.y; wa[6]=t1.z; wa[7]=t1.w;
        t0 = *(const float4*)&W2[128 + hl * 8];
        t1 = *(const float4*)&W2[128 + hl * 8 + 4];
        wb[0]=t0.x; wb[1]=t0.y; wb[2]=t0.z; wb[3]=t0.w;
        wb[4]=t1.x; wb[5]=t1.y; wb[6]=t1.z; wb[7]=t1.w;
    }
    const float bz0 = b2[0], bz1 = b2[1];

    const uint4* __restrict__ U = (const uint4*)g_u;
    const uint4* __restrict__ V = (const uint4*)g_v;
    const int4* __restrict__ EI = (const int4*)g_ei32;

#pragma unroll 4
    for (int it = gw * 2; it < E; it += stride) {
        int4 idx = EI[it >> 1];
        int src = half ? idx.z : idx.x;
        int dst = half ? idx.w : idx.y;
        uint4 ur = U[src * 16 + hl];
        uint4 vr = V[dst * 16 + hl];
        float2 u0 = __half22float2(*(__half2*)&ur.x);
        float2 u1 = __half22float2(*(__half2*)&ur.y);
        float2 u2 = __half22float2(*(__half2*)&ur.z);
        float2 u3 = __half22float2(*(__half2*)&ur.w);
        float2 v0 = __half22float2(*(__half2*)&vr.x);
        float2 v1 = __half22float2(*(__half2*)&vr.y);
        float2 v2 = __half22float2(*(__half2*)&vr.z);
        float2 v3 = __half22float2(*(__half2*)&vr.w);
        float w[8];
        w[0] = u0.x + v0.x; w[1] = u0.y + v0.y;
        w[2] = u1.x + v1.x; w[3] = u1.y + v1.y;
        w[4] = u2.x + v2.x; w[5] = u2.y + v2.y;
        w[6] = u3.x + v3.x; w[7] = u3.y + v3.y;
        float p0 = 0.f, p1 = 0.f;
#pragma unroll
        for (int j = 0; j < 8; j++) {
            float rr = fmaxf(fmaf(a[j], w[j], c[j]), 0.f);
            p0 = fmaf(rr, wa[j], p0);
            p1 = fmaf(rr, wb[j], p1);
        }
#pragma unroll
        for (int o = 8; o > 0; o >>= 1) {
            p0 += __shfl_xor_sync(0xFFFFFFFFu, p0, o);
            p1 += __shfl_xor_sync(0xFFFFFFFFu, p1, o);
        }
        if (hl == 0)
            ((float2*)out)[it + half] = make_float2(p0 + bz0, p1 + bz1);
    }
}

// ---------------- launch ------------------------------------------------
extern "C" void kernel_launch(void* const* d_in, const int* in_sizes, int n_in,
                              void* d_out, int out_size) {
    const float* x = (const float*)d_in[0];
    const long long* ei = (const long long*)d_in[1];
    const float* W1 = (const float*)d_in[2];
    // d_in[3] = b1 : cancels inside BatchNorm, unused
    const float* gamma = (const float*)d_in[4];
    const float* beta = (const float*)d_in[5];
    const float* W2 = (const float*)d_in[6];
    const float* b2 = (const float*)d_in[7];

    const int N = in_sizes[0] / DD;
    const int E = in_sizes[1] / 2;
    const int stride = NBLK_E * WPB * 2;
    const int eb = (E + 255) / 256;

    static int smem_set = 0;
    if (!smem_set) {
        cudaFuncSetAttribute(node_gemm_mma_kernel,
                             cudaFuncAttributeMaxDynamicSharedMemorySize, GEMM_SMEM);
        smem_set = 1;
    }

    prep_kernel<<<128 + eb, 256>>>(W1, ei, E);
    node_gemm_mma_kernel<<<(N + 127) / 128, 256, GEMM_SMEM>>>(x, N);
    edge_stats_kernel<<<NBLK_E, TPB_E>>>(E, stride);
    reduce_finalize_kernel<<<128, 256>>>(gamma, beta, 1.0f / (float)E);
    edge_out_kernel<<<NBLK_E, TPB_E>>>(W2, b2, (float*)d_out, E, stride);
}